// round 9
// baseline (speedup 1.0000x reference)
#include <cuda_runtime.h>
#include <math.h>
#include <stdint.h>

#define NB 2
#define NC 128
#define HG 32
#define L 1024
#define NCOLS 2048   // NC * 16

// ---- scratch (device globals; no allocation allowed) ----
__device__ float g_fd[NB*NC*L];
__device__ float g_bd[NB*NC*L];
__device__ float g_ssq[NB*L];
__device__ float g_rnorm[NB*L];
__device__ float g_corr[NB*L*L];   // M[q,p] = sum_c bd[c,q]*fd[c,p]
__device__ float g_sc[NB*L*L];     // normalized 9-tap scores
__device__ float g_t1[NB*L*L];     // fuse pass 1 output [q][p]
__device__ float g_mmk[L];
__device__ float g_attn[NB*L*L];   // attn [b][p][q] (M-major for GEMM2), tf32-rounded
__device__ float g_W[NB*L*NCOLS];  // raw_w patches [b][q][c*16+u*4+v], tf32-rounded
__device__ float g_OP[NB*L*NCOLS]; // deconv GEMM output [b][p][n]

// ---- helpers ----
__device__ __forceinline__ float to_tf32(float x) {
    uint32_t u;
    asm("cvt.rna.tf32.f32 %0, %1;" : "=r"(u) : "f"(x));
    return __uint_as_float(u);
}
__device__ __forceinline__ uint32_t tf32u(float x) {
    uint32_t u;
    asm("cvt.rna.tf32.f32 %0, %1;" : "=r"(u) : "f"(x));
    return u;
}
__device__ __forceinline__ void cp_async16(uint32_t s, const void* g) {
    asm volatile("cp.async.cg.shared.global [%0], [%1], 16;" :: "r"(s), "l"(g));
}
__device__ __forceinline__ void mma_tf32(float* c, const uint32_t* a, const uint32_t* b) {
    asm volatile(
        "mma.sync.aligned.m16n8k8.row.col.f32.tf32.tf32.f32 "
        "{%0,%1,%2,%3}, {%4,%5,%6,%7}, {%8,%9}, {%0,%1,%2,%3};"
        : "+f"(c[0]), "+f"(c[1]), "+f"(c[2]), "+f"(c[3])
        : "r"(a[0]), "r"(a[1]), "r"(a[2]), "r"(a[3]), "r"(b[0]), "r"(b[1]));
}

// ---- 1. downsample by 2 ----
__global__ void k_down(const float* __restrict__ f, const float* __restrict__ b) {
    int idx = blockIdx.x * blockDim.x + threadIdx.x;
    if (idx >= NB*NC*L) return;
    int x = idx & 31, y = (idx >> 5) & 31, c = (idx >> 10) & 127, bb = idx >> 17;
    size_t base = ((size_t)(bb * NC + c)) * 4096 + (size_t)(2*y) * 64 + 2*x;
    g_fd[idx] = f[base];
    g_bd[idx] = b[base];
}

// ---- 2. per-pixel sum over c of bd^2 ----
__global__ void k_ssq() {
    int idx = blockIdx.x * blockDim.x + threadIdx.x;
    if (idx >= NB*L) return;
    int bb = idx >> 10, q = idx & 1023;
    float s = 0.f;
    const float* p = g_bd + (size_t)bb * NC * L + q;
    #pragma unroll 8
    for (int c = 0; c < NC; c++) { float v = p[(size_t)c * L]; s += v * v; }
    g_ssq[idx] = s;
}

// ---- 3. patch inverse norms (3x3, zero pad) ----
__global__ void k_rnorm() {
    int idx = blockIdx.x * blockDim.x + threadIdx.x;
    if (idx >= NB*L) return;
    int bb = idx >> 10, q = idx & 1023;
    int qy = q >> 5, qx = q & 31;
    float s = 1152.0f * 0.0001f;
    for (int dy = -1; dy <= 1; dy++)
      for (int dx = -1; dx <= 1; dx++) {
        int y = qy + dy, x = qx + dx;
        if (y >= 0 && y < HG && x >= 0 && x < HG) s += g_ssq[bb*L + y*HG + x];
      }
    g_rnorm[idx] = 1.0f / sqrtf(s);
}

// =====================================================================
// GEMM1 via 3xTF32 tensor cores (near-fp32): corr[q,p] = sum_c bd[c,q]*fd[c,p]
// A=bd [K=128][M=1024] K-major, B=fd [K][N=1024] K-major.
// 128x128 CTA tile, 256 threads / 8 warps (warp tile 32x64), BK=32,
// cp.async double buffer. Dekker split in registers.
// =====================================================================
#define G_LD 136
#define G1_STAGE (2*32*G_LD)   // floats per stage (A tile + B tile)

__global__ void __launch_bounds__(256)
mma_gemm1(const float* __restrict__ Aall, const float* __restrict__ Ball,
          float* __restrict__ Call) {
    extern __shared__ float smf[];
    const float* A = Aall + (size_t)blockIdx.z * NC * L;
    const float* B = Ball + (size_t)blockIdx.z * NC * L;
    float* C = Call + (size_t)blockIdx.z * (size_t)L * L;
    const int bm = blockIdx.y * 128, bn = blockIdx.x * 128;
    const int tid = threadIdx.x;
    const int warp = tid >> 5, lane = tid & 31;
    const int wm = (warp & 3) << 5, wn = (warp >> 2) << 6;
    const int r8 = lane >> 2, cc = lane & 3;

    float acc[2][8][4];
    #pragma unroll
    for (int mi = 0; mi < 2; mi++)
      #pragma unroll
      for (int ni = 0; ni < 8; ni++)
        #pragma unroll
        for (int k = 0; k < 4; k++) acc[mi][ni][k] = 0.f;

    const int row = tid >> 3, colb = (tid & 7) * 16;
    const float* ag = A + (size_t)row * L + bm + colb;
    const float* bg = B + (size_t)row * L + bn + colb;
    uint32_t smb = (uint32_t)__cvta_generic_to_shared(smf);

    {
        uint32_t as_ = smb + (uint32_t)(row * G_LD + colb) * 4u;
        uint32_t bs_ = smb + (uint32_t)(32 * G_LD + row * G_LD + colb) * 4u;
        #pragma unroll
        for (int i = 0; i < 4; i++) {
            cp_async16(as_ + i * 16, ag + i * 4);
            cp_async16(bs_ + i * 16, bg + i * 4);
        }
        asm volatile("cp.async.commit_group;");
    }

    const int NKT = NC / 32;  // 4
    int buf = 0;
    for (int kt = 0; kt < NKT; kt++) {
        if (kt + 1 < NKT) {
            int nb = buf ^ 1;
            uint32_t sb = smb + (uint32_t)(nb * G1_STAGE) * 4u;
            const float* ag_ = ag + (size_t)(kt + 1) * 32 * L;
            const float* bg_ = bg + (size_t)(kt + 1) * 32 * L;
            uint32_t as_ = sb + (uint32_t)(row * G_LD + colb) * 4u;
            uint32_t bs_ = sb + (uint32_t)(32 * G_LD + row * G_LD + colb) * 4u;
            #pragma unroll
            for (int i = 0; i < 4; i++) {
                cp_async16(as_ + i * 16, ag_ + i * 4);
                cp_async16(bs_ + i * 16, bg_ + i * 4);
            }
            asm volatile("cp.async.commit_group;");
            asm volatile("cp.async.wait_group 1;");
        } else {
            asm volatile("cp.async.wait_group 0;");
        }
        __syncthreads();

        const float* As = smf + buf * G1_STAGE;
        const float* Bs = As + 32 * G_LD;
        #pragma unroll
        for (int s = 0; s < 4; s++) {
            const int kk = s * 8;
            uint32_t ahi[2][4], alo[2][4], bhi[8][2], blo[8][2];
            #pragma unroll
            for (int mi = 0; mi < 2; mi++) {
                const float* ap = As + (kk + cc) * G_LD + wm + mi * 16 + r8;
                float v0 = ap[0], v1 = ap[8], v2 = ap[4 * G_LD], v3 = ap[4 * G_LD + 8];
                ahi[mi][0] = tf32u(v0); alo[mi][0] = tf32u(v0 - __uint_as_float(ahi[mi][0]));
                ahi[mi][1] = tf32u(v1); alo[mi][1] = tf32u(v1 - __uint_as_float(ahi[mi][1]));
                ahi[mi][2] = tf32u(v2); alo[mi][2] = tf32u(v2 - __uint_as_float(ahi[mi][2]));
                ahi[mi][3] = tf32u(v3); alo[mi][3] = tf32u(v3 - __uint_as_float(ahi[mi][3]));
            }
            #pragma unroll
            for (int ni = 0; ni < 8; ni++) {
                const float* bp = Bs + (kk + cc) * G_LD + wn + ni * 8 + r8;
                float v0 = bp[0], v1 = bp[4 * G_LD];
                bhi[ni][0] = tf32u(v0); blo[ni][0] = tf32u(v0 - __uint_as_float(bhi[ni][0]));
                bhi[ni][1] = tf32u(v1); blo[ni][1] = tf32u(v1 - __uint_as_float(bhi[ni][1]));
            }
            #pragma unroll
            for (int mi = 0; mi < 2; mi++)
                #pragma unroll
                for (int ni = 0; ni < 8; ni++) {
                    mma_tf32(acc[mi][ni], ahi[mi], bhi[ni]);
                    mma_tf32(acc[mi][ni], ahi[mi], blo[ni]);
                    mma_tf32(acc[mi][ni], alo[mi], bhi[ni]);
                }
        }
        __syncthreads();
        buf ^= 1;
    }

    #pragma unroll
    for (int mi = 0; mi < 2; mi++) {
        int r = bm + wm + mi * 16 + r8;
        #pragma unroll
        for (int ni = 0; ni < 8; ni++) {
            int col = bn + wn + ni * 8 + cc * 2;
            *(float2*)(C + (size_t)r * L + col) =
                make_float2(acc[mi][ni][0], acc[mi][ni][1]);
            *(float2*)(C + (size_t)(r + 8) * L + col) =
                make_float2(acc[mi][ni][2], acc[mi][ni][3]);
        }
    }
}

// ---- 5. 9-tap diagonal patch stencil + normalize ----
__global__ void k_scores() {
    int idx = blockIdx.x * blockDim.x + threadIdx.x;
    if (idx >= NB*L*L) return;
    int px = idx & 31, py = (idx >> 5) & 31, qx = (idx >> 10) & 31, qy = (idx >> 15) & 31;
    int bb = idx >> 20;
    const float* M = g_corr + (size_t)bb * L * L;
    float s = 0.f;
    #pragma unroll
    for (int dy = -1; dy <= 1; dy++) {
        int qy2 = qy + dy, py2 = py + dy;
        if (qy2 < 0 || qy2 >= HG || py2 < 0 || py2 >= HG) continue;
        #pragma unroll
        for (int dx = -1; dx <= 1; dx++) {
            int qx2 = qx + dx, px2 = px + dx;
            if (qx2 < 0 || qx2 >= HG || px2 < 0 || px2 >= HG) continue;
            s += M[(size_t)(qy2 * HG + qx2) * L + (py2 * HG + px2)];
        }
    }
    g_sc[idx] = s * g_rnorm[bb * L + qy * HG + qx];
}

// ---- 6. fuse pass 1: diagonal 3-tap on flattened (1024,1024) ----
__global__ void k_fuse1() {
    int idx = blockIdx.x * blockDim.x + threadIdx.x;
    if (idx >= NB*L*L) return;
    int j = idx & 1023, i = (idx >> 10) & 1023;
    float s = g_sc[idx];
    if (i > 0 && j > 0)       s += g_sc[idx - L - 1];
    if (i < 1023 && j < 1023) s += g_sc[idx + L + 1];
    g_t1[idx] = s;
}

// ---- 8. mask gate (batch 0 of mask) ----
__global__ void k_mm(const float* __restrict__ mask) {
    int q = blockIdx.x * blockDim.x + threadIdx.x;
    if (q >= L) return;
    int qy = q >> 5, qx = q & 31;
    float s = 0.f;
    for (int dy = -1; dy <= 1; dy++)
      for (int dx = -1; dx <= 1; dx++) {
        int y = qy + dy, x = qx + dx;
        if (y >= 0 && y < HG && x >= 0 && x < HG)
            s += mask[(size_t)(8 * y) * 256 + 8 * x];
      }
    g_mmk[q] = (s == 0.0f) ? 1.0f : 0.0f;
}

// =====================================================================
// 7+9 fused: fuse pass 2 (diagonal 3-tap in transposed flattening) +
// softmax over q, writing attn TRANSPOSED [p][q] (tf32).
// Block: (32,32) = 1024 threads; one block per (hf, batch).
//   p = hf*32 + tx, q = 32*i + ty  (so hb=i, wb=ty)
//   j2(d) = tx*32 + hf + d  -> col = (j2&31)*32 + (j2>>5)   (coalesced)
//   i2(d) = ty*32 + i  + d  -> row = (i2&31)*32 + (i2>>5)   (uniform per warp)
// =====================================================================
__global__ void __launch_bounds__(1024) k_fuse2_softmax() {
    int bb = blockIdx.y, hf = blockIdx.x;
    int tx = threadIdx.x, ty = threadIdx.y;
    const float* T = g_t1 + (size_t)bb * L * L;
    float* dst = g_attn + (size_t)bb * L * L;
    __shared__ float red[32][33];

    int col[3]; bool jv[3];
    #pragma unroll
    for (int dd = 0; dd < 3; dd++) {
        int j2 = tx * 32 + hf + dd - 1;
        jv[dd] = (j2 >= 0) && (j2 < L);
        int jj = jv[dd] ? j2 : 0;
        col[dd] = (jj & 31) * 32 + (jj >> 5);
    }

    float v[32];
    float mx = -1e30f;
    #pragma unroll
    for (int i = 0; i < 32; i++) {
        float s = 0.f;
        #pragma unroll
        for (int dd = 0; dd < 3; dd++) {
            int i2 = ty * 32 + i + dd - 1;
            bool iv = (i2 >= 0) && (i2 < L);
            if (iv && jv[dd]) {
                int rowi = (i2 & 31) * 32 + (i2 >> 5);
                s += T[(size_t)rowi * L + col[dd]];
            }
        }
        float vv = s * g_mmk[i * 32 + ty] * 10.0f;
        v[i] = vv;
        mx = fmaxf(mx, vv);
    }

    red[ty][tx] = mx; __syncthreads();
    #pragma unroll
    for (int s = 16; s > 0; s >>= 1) {
        if (ty < s) red[ty][tx] = fmaxf(red[ty][tx], red[ty + s][tx]);
        __syncthreads();
    }
    float m = red[0][tx];
    __syncthreads();

    float sum = 0.f;
    #pragma unroll
    for (int i = 0; i < 32; i++) {
        v[i] = expf(v[i] - m);
        sum += v[i];
    }
    red[ty][tx] = sum; __syncthreads();
    #pragma unroll
    for (int s = 16; s > 0; s >>= 1) {
        if (ty < s) red[ty][tx] += red[ty + s][tx];
        __syncthreads();
    }
    float inv = 1.0f / red[0][tx];
    __syncthreads();

    // write transposed: dst[p][q]
    #pragma unroll
    for (int i = 0; i < 32; i++) {
        red[ty][tx] = to_tf32(v[i] * inv * g_mmk[i * 32 + ty]);
        __syncthreads();
        dst[(size_t)(hf * 32 + ty) * L + i * 32 + tx] = red[tx][ty];
        __syncthreads();
    }
}

// ---- 10. build raw_w patch matrix W[b][q][c*16+u*4+v] (tf32-rounded) ----
__global__ void k_buildW(const float* __restrict__ b_in) {
    int idx = blockIdx.x * blockDim.x + threadIdx.x;
    if (idx >= NB*L*NCOLS) return;
    int n = idx & (NCOLS - 1);
    int v = n & 3, u = (n >> 2) & 3, c = n >> 4;
    int q = (idx >> 11) & 1023;
    int bb = idx >> 21;
    int qy = q >> 5, qx = q & 31;
    int by = 2 * qy + u - 1, bx = 2 * qx + v - 1;
    float val = 0.f;
    if (by >= 0 && by < 64 && bx >= 0 && bx < 64)
        val = b_in[((size_t)(bb * NC + c)) * 4096 + (size_t)by * 64 + bx];
    g_W[idx] = to_tf32(val);
}

// =====================================================================
// GEMM2 via tf32 tensor cores:
// OP[p,n] = sum_q attn[p,q] * W[q,n]; A = g_attn [M=1024 p][K=1024 q]
// M-major, B = g_W [K][N=2048] K-major. 128x128 CTA tile, 256 threads /
// 8 warps (warp tile 32x64), BK=32, cp.async double buffer.
// =====================================================================
#define A2_LD 36
#define B2_LD 136
#define G2_STAGE (128*A2_LD + 32*B2_LD)   // 8960 floats per stage

__global__ void __launch_bounds__(256, 2)
mma_gemm2(const float* __restrict__ Aall, const float* __restrict__ Ball,
          float* __restrict__ Call) {
    extern __shared__ float smf[];
    const float* A = Aall + (size_t)blockIdx.z * L * L;
    const float* B = Ball + (size_t)blockIdx.z * (size_t)L * NCOLS;
    float* C = Call + (size_t)blockIdx.z * (size_t)L * NCOLS;
    const int bm = blockIdx.y * 128, bn = blockIdx.x * 128;
    const int tid = threadIdx.x;
    const int warp = tid >> 5, lane = tid & 31;
    const int wm = (warp & 3) << 5, wn = (warp >> 2) << 6;
    const int r8 = lane >> 2, cc = lane & 3;

    float acc[2][8][4];
    #pragma unroll
    for (int mi = 0; mi < 2; mi++)
      #pragma unroll
      for (int ni = 0; ni < 8; ni++)
        #pragma unroll
        for (int k = 0; k < 4; k++) acc[mi][ni][k] = 0.f;

    const int arow = tid >> 1, ak = (tid & 1) * 16;
    const float* ag = A + (size_t)(bm + arow) * L + ak;
    const int brow = tid >> 3, bcol = (tid & 7) * 16;
    const float* bg = B + (size_t)brow * NCOLS + bn + bcol;
    uint32_t smb = (uint32_t)__cvta_generic_to_shared(smf);

    {
        uint32_t as_ = smb + (uint32_t)(arow * A2_LD + ak) * 4u;
        uint32_t bs_ = smb + (uint32_t)(128 * A2_LD + brow * B2_LD + bcol) * 4u;
        #pragma unroll
        for (int i = 0; i < 4; i++) {
            cp_async16(as_ + i * 16, ag + i * 4);
            cp_async16(bs_ + i * 16, bg + i * 4);
        }
        asm volatile("cp.async.commit_group;");
    }

    int buf = 0;
    for (int kt = 0; kt < 32; kt++) {
        if (kt + 1 < 32) {
            int nb = buf ^ 1;
            uint32_t sb = smb + (uint32_t)(nb * G2_STAGE) * 4u;
            const float* ag_ = ag + (kt + 1) * 32;
            const float* bg_ = bg + (size_t)(kt + 1) * 32 * NCOLS;
            uint32_t as_ = sb + (uint32_t)(arow * A2_LD + ak) * 4u;
            uint32_t bs_ = sb + (uint32_t)(128 * A2_LD + brow * B2_LD + bcol) * 4u;
            #pragma unroll
            for (int i = 0; i < 4; i++) {
                cp_async16(as_ + i * 16, ag_ + i * 4);
                cp_async16(bs_ + i * 16, bg_ + i * 4);
            }
            asm volatile("cp.async.commit_group;");
            asm volatile("cp.async.wait_group 1;");
        } else {
            asm volatile("cp.async.wait_group 0;");
        }
        __syncthreads();

        const float* As = smf + buf * G2_STAGE;
        const float* Bs = As + 128 * A2_LD;
        #pragma unroll
        for (int s = 0; s < 4; s++) {
            const int kk = s * 8;
            uint32_t a[2][4], b[8][2];
            #pragma unroll
            for (int mi = 0; mi < 2; mi++) {
                const float* ap = As + (wm + mi * 16 + r8) * A2_LD + kk + cc;
                a[mi][0] = __float_as_uint(ap[0]);
                a[mi][1] = __float_as_uint(ap[8 * A2_LD]);
                a[mi][2] = __float_as_uint(ap[4]);
                a[mi][3] = __float_as_uint(ap[8 * A2_LD + 4]);
            }
            #pragma unroll
            for (int ni = 0; ni < 8; ni++) {
                const float* bp = Bs + (kk + cc) * B2_LD + wn + ni * 8 + r8;
                b[ni][0] = __float_as_uint(bp[0]);
                b[ni][1] = __float_as_uint(bp[4 * B2_LD]);
            }
            #pragma unroll
            for (int mi = 0; mi < 2; mi++)
                #pragma unroll
                for (int ni = 0; ni < 8; ni++)
                    mma_tf32(acc[mi][ni], a[mi], b[ni]);
        }
        __syncthreads();
        buf ^= 1;
    }

    #pragma unroll
    for (int mi = 0; mi < 2; mi++) {
        int r = bm + wm + mi * 16 + r8;
        #pragma unroll
        for (int ni = 0; ni < 8; ni++) {
            int col = bn + wn + ni * 8 + cc * 2;
            *(float2*)(C + (size_t)r * NCOLS + col) =
                make_float2(acc[mi][ni][0], acc[mi][ni][1]);
            *(float2*)(C + (size_t)(r + 8) * NCOLS + col) =
                make_float2(acc[mi][ni][2], acc[mi][ni][3]);
        }
    }
}

// ---- 12. overlap-add gather (deconv epilogue) ----
__global__ void k_gather(float* __restrict__ out) {
    int idx = blockIdx.x * blockDim.x + threadIdx.x;
    if (idx >= NB*NC*4096) return;
    int ox = idx & 63, oy = (idx >> 6) & 63, c = (idx >> 12) & 127, bb = idx >> 19;
    float s = 0.f;
    int ay = (oy + 1) & 1, ax = (ox + 1) & 1;
    #pragma unroll
    for (int uu = 0; uu < 2; uu++) {
        int u = ay + 2 * uu;
        int t = oy + 1 - u;
        if (t < 0) continue;
        int py = t >> 1;
        if (py >= HG) continue;
        #pragma unroll
        for (int vv = 0; vv < 2; vv++) {
            int v = ax + 2 * vv;
            int t2 = ox + 1 - v;
            if (t2 < 0) continue;
            int px = t2 >> 1;
            if (px >= HG) continue;
            s += g_OP[((size_t)bb * L + py * HG + px) * NCOLS + c * 16 + u * 4 + v];
        }
    }
    out[idx] = 0.25f * s;
}

extern "C" void kernel_launch(void* const* d_in, const int* in_sizes, int n_in,
                              void* d_out, int out_size) {
    (void)in_sizes; (void)n_in; (void)out_size;
    const float* f    = (const float*)d_in[0];
    const float* b    = (const float*)d_in[1];
    const float* mask = (const float*)d_in[2];
    float* out = (float*)d_out;

    float *p_fd, *p_bd, *p_corr, *p_attn, *p_W, *p_OP;
    cudaGetSymbolAddress((void**)&p_fd,   g_fd);
    cudaGetSymbolAddress((void**)&p_bd,   g_bd);
    cudaGetSymbolAddress((void**)&p_corr, g_corr);
    cudaGetSymbolAddress((void**)&p_attn, g_attn);
    cudaGetSymbolAddress((void**)&p_W,    g_W);
    cudaGetSymbolAddress((void**)&p_OP,   g_OP);

    const int g1_smem = 2 * G1_STAGE * 4;   // 69632 bytes
    const int g2_smem = 2 * G2_STAGE * 4;   // 71680 bytes
    cudaFuncSetAttribute(mma_gemm1, cudaFuncAttributeMaxDynamicSharedMemorySize, g1_smem);
    cudaFuncSetAttribute(mma_gemm2, cudaFuncAttributeMaxDynamicSharedMemorySize, g2_smem);

    k_down<<<(NB*NC*L + 255) / 256, 256>>>(f, b);
    k_ssq<<<(NB*L + 255) / 256, 256>>>();
    k_rnorm<<<(NB*L + 255) / 256, 256>>>();

    // GEMM1: corr[q,p] = sum_c bd[c,q] * fd[c,p]  (M=N=1024, K=128) — 3xTF32 MMA
    {
        dim3 grid(L / 128, L / 128, NB);
        mma_gemm1<<<grid, 256, g1_smem>>>(p_bd, p_fd, p_corr);
    }

    k_scores<<<(NB*L*L + 255) / 256, 256>>>();
    k_fuse1<<<(NB*L*L + 255) / 256, 256>>>();
    k_mm<<<(L + 255) / 256, 256>>>(mask);
    {
        dim3 grid(32, NB);
        dim3 blk(32, 32);
        k_fuse2_softmax<<<grid, blk>>>();
    }
    k_buildW<<<(NB*L*NCOLS + 255) / 256, 256>>>(b);

    // GEMM2: OP[p,n] = sum_q attn[p,q] * W[q,n]  (M=1024, N=2048, K=1024) — tf32 MMA
    {
        dim3 grid(NCOLS / 128, L / 128, NB);
        mma_gemm2<<<grid, 256, g2_smem>>>(p_attn, p_W, p_OP);
    }

    k_gather<<<(NB*NC*4096 + 255) / 256, 256>>>(out);
}

// round 11
// speedup vs baseline: 1.0887x; 1.0887x over previous
#include <cuda_runtime.h>
#include <math.h>
#include <stdint.h>

#define NB 2
#define NC 128
#define HG 32
#define L 1024
#define NCOLS 2048   // NC * 16

// ---- scratch (device globals; no allocation allowed) ----
__device__ float g_fd[NB*NC*L];
__device__ float g_bd[NB*NC*L];
__device__ float g_ssq[NB*L];
__device__ float g_rnorm[NB*L];
__device__ float g_corr[NB*L*L];   // M[q,p] = sum_c bd[c,q]*fd[c,p]
__device__ float g_t1[NB*L*L];     // fused scores+fuse1 output [q][p]
__device__ float g_mmk[L];
__device__ float g_attn[NB*L*L];   // attn [b][p][q] (M-major for GEMM2), tf32-rounded
__device__ float g_W[NB*L*NCOLS];  // raw_w patches [b][q][c*16+u*4+v], tf32-rounded
__device__ float g_OP[NB*L*NCOLS]; // deconv GEMM output [b][p][n]

// ---- helpers ----
__device__ __forceinline__ float to_tf32(float x) {
    uint32_t u;
    asm("cvt.rna.tf32.f32 %0, %1;" : "=r"(u) : "f"(x));
    return __uint_as_float(u);
}
__device__ __forceinline__ uint32_t tf32u(float x) {
    uint32_t u;
    asm("cvt.rna.tf32.f32 %0, %1;" : "=r"(u) : "f"(x));
    return u;
}
__device__ __forceinline__ void cp_async16(uint32_t s, const void* g) {
    asm volatile("cp.async.cg.shared.global [%0], [%1], 16;" :: "r"(s), "l"(g));
}
__device__ __forceinline__ void mma_tf32(float* c, const uint32_t* a, const uint32_t* b) {
    asm volatile(
        "mma.sync.aligned.m16n8k8.row.col.f32.tf32.tf32.f32 "
        "{%0,%1,%2,%3}, {%4,%5,%6,%7}, {%8,%9}, {%0,%1,%2,%3};"
        : "+f"(c[0]), "+f"(c[1]), "+f"(c[2]), "+f"(c[3])
        : "r"(a[0]), "r"(a[1]), "r"(a[2]), "r"(a[3]), "r"(b[0]), "r"(b[1]));
}

// ---- 1. downsample by 2 ----
__global__ void k_down(const float* __restrict__ f, const float* __restrict__ b) {
    int idx = blockIdx.x * blockDim.x + threadIdx.x;
    if (idx >= NB*NC*L) return;
    int x = idx & 31, y = (idx >> 5) & 31, c = (idx >> 10) & 127, bb = idx >> 17;
    size_t base = ((size_t)(bb * NC + c)) * 4096 + (size_t)(2*y) * 64 + 2*x;
    g_fd[idx] = f[base];
    g_bd[idx] = b[base];
}

// ---- 2. per-pixel sum over c of bd^2 ----
__global__ void k_ssq() {
    int idx = blockIdx.x * blockDim.x + threadIdx.x;
    if (idx >= NB*L) return;
    int bb = idx >> 10, q = idx & 1023;
    float s = 0.f;
    const float* p = g_bd + (size_t)bb * NC * L + q;
    #pragma unroll 8
    for (int c = 0; c < NC; c++) { float v = p[(size_t)c * L]; s += v * v; }
    g_ssq[idx] = s;
}

// ---- 3. patch inverse norms (3x3, zero pad) ----
__global__ void k_rnorm() {
    int idx = blockIdx.x * blockDim.x + threadIdx.x;
    if (idx >= NB*L) return;
    int bb = idx >> 10, q = idx & 1023;
    int qy = q >> 5, qx = q & 31;
    float s = 1152.0f * 0.0001f;
    for (int dy = -1; dy <= 1; dy++)
      for (int dx = -1; dx <= 1; dx++) {
        int y = qy + dy, x = qx + dx;
        if (y >= 0 && y < HG && x >= 0 && x < HG) s += g_ssq[bb*L + y*HG + x];
      }
    g_rnorm[idx] = 1.0f / sqrtf(s);
}

// =====================================================================
// GEMM1 (R8 exact): 3xTF32 mma.sync, 128 threads / 4 warps, 64x64 warp
// tile, BK=32, cp.async double buffer.  corr[q,p] = sum_c bd[c,q]*fd[c,p]
// =====================================================================
#define G_LD 136
#define G1_STAGE (2*32*G_LD)

__global__ void __launch_bounds__(128, 2)
mma_gemm1(const float* __restrict__ Aall, const float* __restrict__ Ball,
          float* __restrict__ Call) {
    extern __shared__ float smf[];
    const float* A = Aall + (size_t)blockIdx.z * NC * L;
    const float* B = Ball + (size_t)blockIdx.z * NC * L;
    float* C = Call + (size_t)blockIdx.z * (size_t)L * L;
    const int bm = blockIdx.y * 128, bn = blockIdx.x * 128;
    const int tid = threadIdx.x;
    const int warp = tid >> 5, lane = tid & 31;
    const int wm = (warp & 1) << 6, wn = (warp >> 1) << 6;
    const int r8 = lane >> 2, cc = lane & 3;

    float acc[4][8][4];
    #pragma unroll
    for (int mi = 0; mi < 4; mi++)
      #pragma unroll
      for (int ni = 0; ni < 8; ni++)
        #pragma unroll
        for (int k = 0; k < 4; k++) acc[mi][ni][k] = 0.f;

    const int row = tid >> 2, colb = (tid & 3) * 4;
    const float* ag = A + (size_t)row * L + bm + colb;
    const float* bg = B + (size_t)row * L + bn + colb;
    uint32_t smb = (uint32_t)__cvta_generic_to_shared(smf);

    {
        uint32_t as_ = smb + (uint32_t)(row * G_LD + colb) * 4u;
        uint32_t bs_ = smb + (uint32_t)(32 * G_LD + row * G_LD + colb) * 4u;
        #pragma unroll
        for (int i = 0; i < 8; i++) {
            cp_async16(as_ + i * 64, ag + i * 16);
            cp_async16(bs_ + i * 64, bg + i * 16);
        }
        asm volatile("cp.async.commit_group;");
    }

    const int NKT = NC / 32;  // 4
    int buf = 0;
    for (int kt = 0; kt < NKT; kt++) {
        if (kt + 1 < NKT) {
            int nb = buf ^ 1;
            uint32_t sb = smb + (uint32_t)(nb * G1_STAGE) * 4u;
            const float* ag_ = ag + (size_t)(kt + 1) * 32 * L;
            const float* bg_ = bg + (size_t)(kt + 1) * 32 * L;
            uint32_t as_ = sb + (uint32_t)(row * G_LD + colb) * 4u;
            uint32_t bs_ = sb + (uint32_t)(32 * G_LD + row * G_LD + colb) * 4u;
            #pragma unroll
            for (int i = 0; i < 8; i++) {
                cp_async16(as_ + i * 64, ag_ + i * 16);
                cp_async16(bs_ + i * 64, bg_ + i * 16);
            }
            asm volatile("cp.async.commit_group;");
            asm volatile("cp.async.wait_group 1;");
        } else {
            asm volatile("cp.async.wait_group 0;");
        }
        __syncthreads();

        const float* As = smf + buf * G1_STAGE;
        const float* Bs = As + 32 * G_LD;
        #pragma unroll
        for (int s = 0; s < 4; s++) {
            const int kk = s * 8;
            uint32_t ahi[4][4], alo[4][4], bhi[8][2], blo[8][2];
            #pragma unroll
            for (int mi = 0; mi < 4; mi++) {
                const float* ap = As + (kk + cc) * G_LD + wm + mi * 16 + r8;
                float v0 = ap[0], v1 = ap[8], v2 = ap[4 * G_LD], v3 = ap[4 * G_LD + 8];
                ahi[mi][0] = tf32u(v0); alo[mi][0] = tf32u(v0 - __uint_as_float(ahi[mi][0]));
                ahi[mi][1] = tf32u(v1); alo[mi][1] = tf32u(v1 - __uint_as_float(ahi[mi][1]));
                ahi[mi][2] = tf32u(v2); alo[mi][2] = tf32u(v2 - __uint_as_float(ahi[mi][2]));
                ahi[mi][3] = tf32u(v3); alo[mi][3] = tf32u(v3 - __uint_as_float(ahi[mi][3]));
            }
            #pragma unroll
            for (int ni = 0; ni < 8; ni++) {
                const float* bp = Bs + (kk + cc) * G_LD + wn + ni * 8 + r8;
                float v0 = bp[0], v1 = bp[4 * G_LD];
                bhi[ni][0] = tf32u(v0); blo[ni][0] = tf32u(v0 - __uint_as_float(bhi[ni][0]));
                bhi[ni][1] = tf32u(v1); blo[ni][1] = tf32u(v1 - __uint_as_float(bhi[ni][1]));
            }
            #pragma unroll
            for (int mi = 0; mi < 4; mi++)
                #pragma unroll
                for (int ni = 0; ni < 8; ni++) {
                    mma_tf32(acc[mi][ni], ahi[mi], bhi[ni]);
                    mma_tf32(acc[mi][ni], ahi[mi], blo[ni]);
                    mma_tf32(acc[mi][ni], alo[mi], bhi[ni]);
                }
        }
        __syncthreads();
        buf ^= 1;
    }

    #pragma unroll
    for (int mi = 0; mi < 4; mi++) {
        int r = bm + wm + mi * 16 + r8;
        #pragma unroll
        for (int ni = 0; ni < 8; ni++) {
            int col = bn + wn + ni * 8 + cc * 2;
            *(float2*)(C + (size_t)r * L + col) =
                make_float2(acc[mi][ni][0], acc[mi][ni][1]);
            *(float2*)(C + (size_t)(r + 8) * L + col) =
                make_float2(acc[mi][ni][2], acc[mi][ni][3]);
        }
    }
}

// =====================================================================
// 5+6 fused: 9-tap patch stencil + normalize (scores), then fuse pass 1
// (diagonal 3-tap on the full 1024x1024 matrix), writing g_t1 directly.
// Block = 256 threads (32,8), output tile 32(q) x 32(p).
// sc halo tile 34x34 in smem; zero-fill makes fuse1 guards implicit.
// =====================================================================
__global__ void __launch_bounds__(256) k_scores_fuse1() {
    __shared__ float ssc[34][35];
    const int bb = blockIdx.z;
    const int p0 = blockIdx.x * 32, q0 = blockIdx.y * 32;
    const float* M = g_corr + (size_t)bb * L * L;
    const float* rn = g_rnorm + bb * L;
    float* dst = g_t1 + (size_t)bb * L * L;
    const int tid = threadIdx.y * 32 + threadIdx.x;

    // compute sc halo tile: a in [0,34) -> q = q0-1+a ; b in [0,34) -> p = p0-1+b
    for (int idx = tid; idx < 34 * 34; idx += 256) {
        int a = idx / 34, b = idx - a * 34;
        int q = q0 - 1 + a, p = p0 - 1 + b;
        float s = 0.f;
        if (q >= 0 && q < L && p >= 0 && p < L) {
            int qy = q >> 5, qx = q & 31, py = p >> 5, px = p & 31;
            #pragma unroll
            for (int dy = -1; dy <= 1; dy++) {
                int qy2 = qy + dy, py2 = py + dy;
                if (qy2 < 0 || qy2 >= HG || py2 < 0 || py2 >= HG) continue;
                #pragma unroll
                for (int dx = -1; dx <= 1; dx++) {
                    int qx2 = qx + dx, px2 = px + dx;
                    if (qx2 < 0 || qx2 >= HG || px2 < 0 || px2 >= HG) continue;
                    s += M[(size_t)(qy2 * HG + qx2) * L + (py2 * HG + px2)];
                }
            }
            s *= rn[q];
        }
        ssc[a][b] = s;
    }
    __syncthreads();

    // fuse1: t1[q][p] = sc[q][p] + sc[q-1][p-1] + sc[q+1][p+1]
    int tx = threadIdx.x, ty = threadIdx.y;
    #pragma unroll
    for (int r = 0; r < 4; r++) {
        int a = ty + 8 * r + 1, b = tx + 1;
        float s = ssc[a][b] + ssc[a - 1][b - 1] + ssc[a + 1][b + 1];
        dst[(size_t)(q0 + ty + 8 * r) * L + p0 + tx] = s;
    }
}

// ---- 8. mask gate (batch 0 of mask) ----
__global__ void k_mm(const float* __restrict__ mask) {
    int q = blockIdx.x * blockDim.x + threadIdx.x;
    if (q >= L) return;
    int qy = q >> 5, qx = q & 31;
    float s = 0.f;
    for (int dy = -1; dy <= 1; dy++)
      for (int dx = -1; dx <= 1; dx++) {
        int y = qy + dy, x = qx + dx;
        if (y >= 0 && y < HG && x >= 0 && x < HG)
            s += mask[(size_t)(8 * y) * 256 + 8 * x];
      }
    g_mmk[q] = (s == 0.0f) ? 1.0f : 0.0f;
}

// =====================================================================
// 7+9 fused: fuse pass 2 (diagonal 3-tap in transposed flattening) +
// softmax over q, writing attn TRANSPOSED [p][q] (tf32).
// Block: (32,32); one block per (hf, batch).
// =====================================================================
__global__ void __launch_bounds__(1024) k_fuse2_softmax() {
    int bb = blockIdx.y, hf = blockIdx.x;
    int tx = threadIdx.x, ty = threadIdx.y;
    const float* T = g_t1 + (size_t)bb * L * L;
    float* dst = g_attn + (size_t)bb * L * L;
    __shared__ float red[32][33];

    int col[3]; bool jv[3];
    #pragma unroll
    for (int dd = 0; dd < 3; dd++) {
        int j2 = tx * 32 + hf + dd - 1;
        jv[dd] = (j2 >= 0) && (j2 < L);
        int jj = jv[dd] ? j2 : 0;
        col[dd] = (jj & 31) * 32 + (jj >> 5);
    }

    float v[32];
    float mx = -1e30f;
    #pragma unroll
    for (int i = 0; i < 32; i++) {
        float s = 0.f;
        #pragma unroll
        for (int dd = 0; dd < 3; dd++) {
            int i2 = ty * 32 + i + dd - 1;
            bool iv = (i2 >= 0) && (i2 < L);
            if (iv && jv[dd]) {
                int rowi = (i2 & 31) * 32 + (i2 >> 5);
                s += T[(size_t)rowi * L + col[dd]];
            }
        }
        float vv = s * g_mmk[i * 32 + ty] * 10.0f;
        v[i] = vv;
        mx = fmaxf(mx, vv);
    }

    red[ty][tx] = mx; __syncthreads();
    #pragma unroll
    for (int s = 16; s > 0; s >>= 1) {
        if (ty < s) red[ty][tx] = fmaxf(red[ty][tx], red[ty + s][tx]);
        __syncthreads();
    }
    float m = red[0][tx];
    __syncthreads();

    float sum = 0.f;
    #pragma unroll
    for (int i = 0; i < 32; i++) {
        v[i] = expf(v[i] - m);
        sum += v[i];
    }
    red[ty][tx] = sum; __syncthreads();
    #pragma unroll
    for (int s = 16; s > 0; s >>= 1) {
        if (ty < s) red[ty][tx] += red[ty + s][tx];
        __syncthreads();
    }
    float inv = 1.0f / red[0][tx];
    __syncthreads();

    // write transposed: dst[p][q]
    #pragma unroll
    for (int i = 0; i < 32; i++) {
        red[ty][tx] = to_tf32(v[i] * inv * g_mmk[i * 32 + ty]);
        __syncthreads();
        dst[(size_t)(hf * 32 + ty) * L + i * 32 + tx] = red[tx][ty];
        __syncthreads();
    }
}

// ---- 10. build raw_w patch matrix W[b][q][c*16+u*4+v] (tf32-rounded) ----
__global__ void k_buildW(const float* __restrict__ b_in) {
    int idx = blockIdx.x * blockDim.x + threadIdx.x;
    if (idx >= NB*L*NCOLS) return;
    int n = idx & (NCOLS - 1);
    int v = n & 3, u = (n >> 2) & 3, c = n >> 4;
    int q = (idx >> 11) & 1023;
    int bb = idx >> 21;
    int qy = q >> 5, qx = q & 31;
    int by = 2 * qy + u - 1, bx = 2 * qx + v - 1;
    float val = 0.f;
    if (by >= 0 && by < 64 && bx >= 0 && bx < 64)
        val = b_in[((size_t)(bb * NC + c)) * 4096 + (size_t)by * 64 + bx];
    g_W[idx] = to_tf32(val);
}

// =====================================================================
// GEMM2 (R7 exact): tf32 mma.sync, 128 threads / 4 warps, 64x64 warp
// tile.  OP[p,n] = sum_q attn[p,q] * W[q,n]; A = g_attn [M=1024 p][K]
// M-major, B = g_W [K][N=2048] K-major.  BK=32, cp.async double buffer.
// =====================================================================
#define G2_LDA 36
#define G2_LDB 136
#define G2_STAGE (128*G2_LDA + 32*G2_LDB)   // floats per stage

__global__ void __launch_bounds__(128, 2)
mma_gemm2(const float* __restrict__ Aall, const float* __restrict__ Ball,
          float* __restrict__ Call) {
    extern __shared__ float smf[];
    const float* A = Aall + (size_t)blockIdx.z * L * L;
    const float* B = Ball + (size_t)blockIdx.z * (size_t)L * NCOLS;
    float* C = Call + (size_t)blockIdx.z * (size_t)L * NCOLS;
    const int bm = blockIdx.y * 128, bn = blockIdx.x * 128;
    const int tid = threadIdx.x;
    const int warp = tid >> 5, lane = tid & 31;
    const int wm = (warp & 1) << 6, wn = (warp >> 1) << 6;
    const int r8 = lane >> 2, cc = lane & 3;

    float acc[4][8][4];
    #pragma unroll
    for (int mi = 0; mi < 4; mi++)
      #pragma unroll
      for (int ni = 0; ni < 8; ni++)
        #pragma unroll
        for (int k = 0; k < 4; k++) acc[mi][ni][k] = 0.f;

    const float* agp = A + (size_t)(bm + tid) * L;           // row of A, +k0
    const int brow = tid >> 2;
    const int bc = (tid & 3) * 4;                            // float col base
    const float* bgp = B + (size_t)brow * NCOLS + bn + bc;   // +k0*NCOLS

    uint32_t smbase = (uint32_t)__cvta_generic_to_shared(smf);

    // prologue: stage 0
    {
        uint32_t as_ = smbase + (uint32_t)(tid * G2_LDA) * 4u;
        #pragma unroll
        for (int i = 0; i < 8; i++) cp_async16(as_ + i * 16, agp + i * 4);
        uint32_t bs_ = smbase + (uint32_t)(128 * G2_LDA + brow * G2_LDB + bc) * 4u;
        #pragma unroll
        for (int i = 0; i < 8; i++) cp_async16(bs_ + i * 64, bgp + i * 16);
        asm volatile("cp.async.commit_group;");
    }

    int buf = 0;
    for (int kt = 0; kt < 32; kt++) {
        if (kt + 1 < 32) {
            int nb = buf ^ 1;
            uint32_t sb = smbase + (uint32_t)(nb * G2_STAGE) * 4u;
            const float* ag_ = agp + (kt + 1) * 32;
            uint32_t as_ = sb + (uint32_t)(tid * G2_LDA) * 4u;
            #pragma unroll
            for (int i = 0; i < 8; i++) cp_async16(as_ + i * 16, ag_ + i * 4);
            const float* bg_ = bgp + (size_t)(kt + 1) * 32 * NCOLS;
            uint32_t bs_ = sb + (uint32_t)(128 * G2_LDA + brow * G2_LDB + bc) * 4u;
            #pragma unroll
            for (int i = 0; i < 8; i++) cp_async16(bs_ + i * 64, bg_ + i * 16);
            asm volatile("cp.async.commit_group;");
            asm volatile("cp.async.wait_group 1;");
        } else {
            asm volatile("cp.async.wait_group 0;");
        }
        __syncthreads();

        const float* As = smf + buf * G2_STAGE;
        const float* Bs = As + 128 * G2_LDA;
        #pragma unroll
        for (int s = 0; s < 4; s++) {
            const int kk = s * 8;
            uint32_t a[4][4], b[8][2];
            #pragma unroll
            for (int mi = 0; mi < 4; mi++) {
                const float* ap = As + (wm + mi * 16 + r8) * G2_LDA + kk + cc;
                a[mi][0] = __float_as_uint(ap[0]);
                a[mi][1] = __float_as_uint(ap[8 * G2_LDA]);
                a[mi][2] = __float_as_uint(ap[4]);
                a[mi][3] = __float_as_uint(ap[8 * G2_LDA + 4]);
            }
            #pragma unroll
            for (int ni = 0; ni < 8; ni++) {
                const float* bp = Bs + (kk + cc) * G2_LDB + wn + ni * 8 + r8;
                b[ni][0] = __float_as_uint(bp[0]);
                b[ni][1] = __float_as_uint(bp[4 * G2_LDB]);
            }
            #pragma unroll
            for (int mi = 0; mi < 4; mi++)
                #pragma unroll
                for (int ni = 0; ni < 8; ni++)
                    mma_tf32(acc[mi][ni], a[mi], b[ni]);
        }
        __syncthreads();
        buf ^= 1;
    }

    // epilogue
    #pragma unroll
    for (int mi = 0; mi < 4; mi++) {
        int row = bm + wm + mi * 16 + r8;
        #pragma unroll
        for (int ni = 0; ni < 8; ni++) {
            int col = bn + wn + ni * 8 + cc * 2;
            *(float2*)(C + (size_t)row * NCOLS + col) =
                make_float2(acc[mi][ni][0], acc[mi][ni][1]);
            *(float2*)(C + (size_t)(row + 8) * NCOLS + col) =
                make_float2(acc[mi][ni][2], acc[mi][ni][3]);
        }
    }
}

// ---- 12. overlap-add gather (deconv epilogue) ----
__global__ void k_gather(float* __restrict__ out) {
    int idx = blockIdx.x * blockDim.x + threadIdx.x;
    if (idx >= NB*NC*4096) return;
    int ox = idx & 63, oy = (idx >> 6) & 63, c = (idx >> 12) & 127, bb = idx >> 19;
    float s = 0.f;
    int ay = (oy + 1) & 1, ax = (ox + 1) & 1;
    #pragma unroll
    for (int uu = 0; uu < 2; uu++) {
        int u = ay + 2 * uu;
        int t = oy + 1 - u;
        if (t < 0) continue;
        int py = t >> 1;
        if (py >= HG) continue;
        #pragma unroll
        for (int vv = 0; vv < 2; vv++) {
            int v = ax + 2 * vv;
            int t2 = ox + 1 - v;
            if (t2 < 0) continue;
            int px = t2 >> 1;
            if (px >= HG) continue;
            s += g_OP[((size_t)bb * L + py * HG + px) * NCOLS + c * 16 + u * 4 + v];
        }
    }
    out[idx] = 0.25f * s;
}

extern "C" void kernel_launch(void* const* d_in, const int* in_sizes, int n_in,
                              void* d_out, int out_size) {
    (void)in_sizes; (void)n_in; (void)out_size;
    const float* f    = (const float*)d_in[0];
    const float* b    = (const float*)d_in[1];
    const float* mask = (const float*)d_in[2];
    float* out = (float*)d_out;

    float *p_fd, *p_bd, *p_corr, *p_attn, *p_W, *p_OP;
    cudaGetSymbolAddress((void**)&p_fd,   g_fd);
    cudaGetSymbolAddress((void**)&p_bd,   g_bd);
    cudaGetSymbolAddress((void**)&p_corr, g_corr);
    cudaGetSymbolAddress((void**)&p_attn, g_attn);
    cudaGetSymbolAddress((void**)&p_W,    g_W);
    cudaGetSymbolAddress((void**)&p_OP,   g_OP);

    const int g1_smem = 2 * G1_STAGE * 4;   // 69632 bytes
    const int g2_smem = 2 * G2_STAGE * 4;   // 71680 bytes
    cudaFuncSetAttribute(mma_gemm1, cudaFuncAttributeMaxDynamicSharedMemorySize, g1_smem);
    cudaFuncSetAttribute(mma_gemm2, cudaFuncAttributeMaxDynamicSharedMemorySize, g2_smem);

    k_down<<<(NB*NC*L + 255) / 256, 256>>>(f, b);
    k_ssq<<<(NB*L + 255) / 256, 256>>>();
    k_rnorm<<<(NB*L + 255) / 256, 256>>>();

    // GEMM1: corr[q,p] (M=N=1024, K=128) — 3xTF32 mma.sync
    {
        dim3 grid(L / 128, L / 128, NB);
        mma_gemm1<<<grid, 128, g1_smem>>>(p_bd, p_fd, p_corr);
    }

    // fused scores + fuse1
    {
        dim3 grid(32, 32, NB);
        dim3 blk(32, 8);
        k_scores_fuse1<<<grid, blk>>>();
    }
    k_mm<<<(L + 255) / 256, 256>>>(mask);
    {
        dim3 grid(32, NB);
        dim3 blk(32, 32);
        k_fuse2_softmax<<<grid, blk>>>();
    }
    k_buildW<<<(NB*L*NCOLS + 255) / 256, 256>>>(b);

    // GEMM2: OP[p,n] (M=1024, N=2048, K=1024) — tf32 MMA
    {
        dim3 grid(NCOLS / 128, L / 128, NB);
        mma_gemm2<<<grid, 128, g2_smem>>>(p_attn, p_W, p_OP);
    }

    k_gather<<<(NB*NC*4096 + 255) / 256, 256>>>(out);
}

// round 12
// speedup vs baseline: 1.3564x; 1.2459x over previous
#include <cuda_runtime.h>
#include <cuda_fp16.h>
#include <math.h>
#include <stdint.h>

#define NB 2
#define NC 128
#define HG 32
#define L 1024
#define NCOLS 2048   // NC * 16

// ---- scratch (device globals; no allocation allowed) ----
__device__ float g_fd[NB*NC*L];
__device__ float g_bd[NB*NC*L];
__device__ float g_ssq[NB*L];
__device__ float g_rnorm[NB*L];
__device__ float g_corr[NB*L*L];     // M[q,p] = sum_c bd[c,q]*fd[c,p]
__device__ float g_t1[NB*L*L];       // fused scores+fuse1 output [q][p]
__device__ float g_mmk[L];
__device__ __half g_attnh[NB*L*L];      // attn [b][p][q] (M-major), fp16
__device__ __half g_Wh[NB*NCOLS*L];     // W [b][n][q] (N-major), fp16
__device__ float g_OP[NB*L*NCOLS];      // deconv GEMM output [b][p][n]

// ---- helpers ----
__device__ __forceinline__ uint32_t tf32u(float x) {
    uint32_t u;
    asm("cvt.rna.tf32.f32 %0, %1;" : "=r"(u) : "f"(x));
    return u;
}
__device__ __forceinline__ void cp_async16(uint32_t s, const void* g) {
    asm volatile("cp.async.cg.shared.global [%0], [%1], 16;" :: "r"(s), "l"(g));
}
__device__ __forceinline__ void mma_tf32(float* c, const uint32_t* a, const uint32_t* b) {
    asm volatile(
        "mma.sync.aligned.m16n8k8.row.col.f32.tf32.tf32.f32 "
        "{%0,%1,%2,%3}, {%4,%5,%6,%7}, {%8,%9}, {%0,%1,%2,%3};"
        : "+f"(c[0]), "+f"(c[1]), "+f"(c[2]), "+f"(c[3])
        : "r"(a[0]), "r"(a[1]), "r"(a[2]), "r"(a[3]), "r"(b[0]), "r"(b[1]));
}
__device__ __forceinline__ void mma_f16(float* c, const uint32_t* a, const uint32_t* b) {
    asm volatile(
        "mma.sync.aligned.m16n8k16.row.col.f32.f16.f16.f32 "
        "{%0,%1,%2,%3}, {%4,%5,%6,%7}, {%8,%9}, {%0,%1,%2,%3};"
        : "+f"(c[0]), "+f"(c[1]), "+f"(c[2]), "+f"(c[3])
        : "r"(a[0]), "r"(a[1]), "r"(a[2]), "r"(a[3]), "r"(b[0]), "r"(b[1]));
}

// ---- 1. downsample by 2 ----
__global__ void k_down(const float* __restrict__ f, const float* __restrict__ b) {
    int idx = blockIdx.x * blockDim.x + threadIdx.x;
    if (idx >= NB*NC*L) return;
    int x = idx & 31, y = (idx >> 5) & 31, c = (idx >> 10) & 127, bb = idx >> 17;
    size_t base = ((size_t)(bb * NC + c)) * 4096 + (size_t)(2*y) * 64 + 2*x;
    g_fd[idx] = f[base];
    g_bd[idx] = b[base];
}

// ---- 2. per-pixel sum over c of bd^2 ----
__global__ void k_ssq() {
    int idx = blockIdx.x * blockDim.x + threadIdx.x;
    if (idx >= NB*L) return;
    int bb = idx >> 10, q = idx & 1023;
    float s = 0.f;
    const float* p = g_bd + (size_t)bb * NC * L + q;
    #pragma unroll 8
    for (int c = 0; c < NC; c++) { float v = p[(size_t)c * L]; s += v * v; }
    g_ssq[idx] = s;
}

// ---- 3. patch inverse norms (3x3, zero pad) ----
__global__ void k_rnorm() {
    int idx = blockIdx.x * blockDim.x + threadIdx.x;
    if (idx >= NB*L) return;
    int bb = idx >> 10, q = idx & 1023;
    int qy = q >> 5, qx = q & 31;
    float s = 1152.0f * 0.0001f;
    for (int dy = -1; dy <= 1; dy++)
      for (int dx = -1; dx <= 1; dx++) {
        int y = qy + dy, x = qx + dx;
        if (y >= 0 && y < HG && x >= 0 && x < HG) s += g_ssq[bb*L + y*HG + x];
      }
    g_rnorm[idx] = 1.0f / sqrtf(s);
}

// =====================================================================
// GEMM1 (R8 exact): 3xTF32 mma.sync, 128 threads / 4 warps, 64x64 warp
// tile, BK=32, cp.async double buffer.  corr[q,p] = sum_c bd[c,q]*fd[c,p]
// =====================================================================
#define G_LD 136
#define G1_STAGE (2*32*G_LD)

__global__ void __launch_bounds__(128, 2)
mma_gemm1(const float* __restrict__ Aall, const float* __restrict__ Ball,
          float* __restrict__ Call) {
    extern __shared__ float smf[];
    const float* A = Aall + (size_t)blockIdx.z * NC * L;
    const float* B = Ball + (size_t)blockIdx.z * NC * L;
    float* C = Call + (size_t)blockIdx.z * (size_t)L * L;
    const int bm = blockIdx.y * 128, bn = blockIdx.x * 128;
    const int tid = threadIdx.x;
    const int warp = tid >> 5, lane = tid & 31;
    const int wm = (warp & 1) << 6, wn = (warp >> 1) << 6;
    const int r8 = lane >> 2, cc = lane & 3;

    float acc[4][8][4];
    #pragma unroll
    for (int mi = 0; mi < 4; mi++)
      #pragma unroll
      for (int ni = 0; ni < 8; ni++)
        #pragma unroll
        for (int k = 0; k < 4; k++) acc[mi][ni][k] = 0.f;

    const int row = tid >> 2, colb = (tid & 3) * 4;
    const float* ag = A + (size_t)row * L + bm + colb;
    const float* bg = B + (size_t)row * L + bn + colb;
    uint32_t smb = (uint32_t)__cvta_generic_to_shared(smf);

    {
        uint32_t as_ = smb + (uint32_t)(row * G_LD + colb) * 4u;
        uint32_t bs_ = smb + (uint32_t)(32 * G_LD + row * G_LD + colb) * 4u;
        #pragma unroll
        for (int i = 0; i < 8; i++) {
            cp_async16(as_ + i * 64, ag + i * 16);
            cp_async16(bs_ + i * 64, bg + i * 16);
        }
        asm volatile("cp.async.commit_group;");
    }

    const int NKT = NC / 32;  // 4
    int buf = 0;
    for (int kt = 0; kt < NKT; kt++) {
        if (kt + 1 < NKT) {
            int nb = buf ^ 1;
            uint32_t sb = smb + (uint32_t)(nb * G1_STAGE) * 4u;
            const float* ag_ = ag + (size_t)(kt + 1) * 32 * L;
            const float* bg_ = bg + (size_t)(kt + 1) * 32 * L;
            uint32_t as_ = sb + (uint32_t)(row * G_LD + colb) * 4u;
            uint32_t bs_ = sb + (uint32_t)(32 * G_LD + row * G_LD + colb) * 4u;
            #pragma unroll
            for (int i = 0; i < 8; i++) {
                cp_async16(as_ + i * 64, ag_ + i * 16);
                cp_async16(bs_ + i * 64, bg_ + i * 16);
            }
            asm volatile("cp.async.commit_group;");
            asm volatile("cp.async.wait_group 1;");
        } else {
            asm volatile("cp.async.wait_group 0;");
        }
        __syncthreads();

        const float* As = smf + buf * G1_STAGE;
        const float* Bs = As + 32 * G_LD;
        #pragma unroll
        for (int s = 0; s < 4; s++) {
            const int kk = s * 8;
            uint32_t ahi[4][4], alo[4][4], bhi[8][2], blo[8][2];
            #pragma unroll
            for (int mi = 0; mi < 4; mi++) {
                const float* ap = As + (kk + cc) * G_LD + wm + mi * 16 + r8;
                float v0 = ap[0], v1 = ap[8], v2 = ap[4 * G_LD], v3 = ap[4 * G_LD + 8];
                ahi[mi][0] = tf32u(v0); alo[mi][0] = tf32u(v0 - __uint_as_float(ahi[mi][0]));
                ahi[mi][1] = tf32u(v1); alo[mi][1] = tf32u(v1 - __uint_as_float(ahi[mi][1]));
                ahi[mi][2] = tf32u(v2); alo[mi][2] = tf32u(v2 - __uint_as_float(ahi[mi][2]));
                ahi[mi][3] = tf32u(v3); alo[mi][3] = tf32u(v3 - __uint_as_float(ahi[mi][3]));
            }
            #pragma unroll
            for (int ni = 0; ni < 8; ni++) {
                const float* bp = Bs + (kk + cc) * G_LD + wn + ni * 8 + r8;
                float v0 = bp[0], v1 = bp[4 * G_LD];
                bhi[ni][0] = tf32u(v0); blo[ni][0] = tf32u(v0 - __uint_as_float(bhi[ni][0]));
                bhi[ni][1] = tf32u(v1); blo[ni][1] = tf32u(v1 - __uint_as_float(bhi[ni][1]));
            }
            #pragma unroll
            for (int mi = 0; mi < 4; mi++)
                #pragma unroll
                for (int ni = 0; ni < 8; ni++) {
                    mma_tf32(acc[mi][ni], ahi[mi], bhi[ni]);
                    mma_tf32(acc[mi][ni], ahi[mi], blo[ni]);
                    mma_tf32(acc[mi][ni], alo[mi], bhi[ni]);
                }
        }
        __syncthreads();
        buf ^= 1;
    }

    #pragma unroll
    for (int mi = 0; mi < 4; mi++) {
        int r = bm + wm + mi * 16 + r8;
        #pragma unroll
        for (int ni = 0; ni < 8; ni++) {
            int col = bn + wn + ni * 8 + cc * 2;
            *(float2*)(C + (size_t)r * L + col) =
                make_float2(acc[mi][ni][0], acc[mi][ni][1]);
            *(float2*)(C + (size_t)(r + 8) * L + col) =
                make_float2(acc[mi][ni][2], acc[mi][ni][3]);
        }
    }
}

// =====================================================================
// 5+6 fused: scores (9-tap + normalize) + fuse1 (diagonal 3-tap),
// writing g_t1 directly.  Block (32,8); output tile 32(q) x 32(p).
// =====================================================================
__global__ void __launch_bounds__(256) k_scores_fuse1() {
    __shared__ float ssc[34][35];
    const int bb = blockIdx.z;
    const int p0 = blockIdx.x * 32, q0 = blockIdx.y * 32;
    const float* M = g_corr + (size_t)bb * L * L;
    const float* rn = g_rnorm + bb * L;
    float* dst = g_t1 + (size_t)bb * L * L;
    const int tid = threadIdx.y * 32 + threadIdx.x;

    for (int idx = tid; idx < 34 * 34; idx += 256) {
        int a = idx / 34, b = idx - a * 34;
        int q = q0 - 1 + a, p = p0 - 1 + b;
        float s = 0.f;
        if (q >= 0 && q < L && p >= 0 && p < L) {
            int qy = q >> 5, qx = q & 31, py = p >> 5, px = p & 31;
            #pragma unroll
            for (int dy = -1; dy <= 1; dy++) {
                int qy2 = qy + dy, py2 = py + dy;
                if (qy2 < 0 || qy2 >= HG || py2 < 0 || py2 >= HG) continue;
                #pragma unroll
                for (int dx = -1; dx <= 1; dx++) {
                    int qx2 = qx + dx, px2 = px + dx;
                    if (qx2 < 0 || qx2 >= HG || px2 < 0 || px2 >= HG) continue;
                    s += M[(size_t)(qy2 * HG + qx2) * L + (py2 * HG + px2)];
                }
            }
            s *= rn[q];
        }
        ssc[a][b] = s;
    }
    __syncthreads();

    int tx = threadIdx.x, ty = threadIdx.y;
    #pragma unroll
    for (int r = 0; r < 4; r++) {
        int a = ty + 8 * r + 1, b = tx + 1;
        float s = ssc[a][b] + ssc[a - 1][b - 1] + ssc[a + 1][b + 1];
        dst[(size_t)(q0 + ty + 8 * r) * L + p0 + tx] = s;
    }
}

// ---- 8. mask gate (batch 0 of mask) ----
__global__ void k_mm(const float* __restrict__ mask) {
    int q = blockIdx.x * blockDim.x + threadIdx.x;
    if (q >= L) return;
    int qy = q >> 5, qx = q & 31;
    float s = 0.f;
    for (int dy = -1; dy <= 1; dy++)
      for (int dx = -1; dx <= 1; dx++) {
        int y = qy + dy, x = qx + dx;
        if (y >= 0 && y < HG && x >= 0 && x < HG)
            s += mask[(size_t)(8 * y) * 256 + 8 * x];
      }
    g_mmk[q] = (s == 0.0f) ? 1.0f : 0.0f;
}

// =====================================================================
// 7+9 fused: fuse pass 2 + softmax over q, writing attn TRANSPOSED
// [p][q] as fp16.  Block (32,32); one block per (hf, batch).
// =====================================================================
__global__ void __launch_bounds__(1024) k_fuse2_softmax() {
    int bb = blockIdx.y, hf = blockIdx.x;
    int tx = threadIdx.x, ty = threadIdx.y;
    const float* T = g_t1 + (size_t)bb * L * L;
    __half* dst = g_attnh + (size_t)bb * L * L;
    __shared__ float red[32][33];

    int col[3]; bool jv[3];
    #pragma unroll
    for (int dd = 0; dd < 3; dd++) {
        int j2 = tx * 32 + hf + dd - 1;
        jv[dd] = (j2 >= 0) && (j2 < L);
        int jj = jv[dd] ? j2 : 0;
        col[dd] = (jj & 31) * 32 + (jj >> 5);
    }

    float v[32];
    float mx = -1e30f;
    #pragma unroll
    for (int i = 0; i < 32; i++) {
        float s = 0.f;
        #pragma unroll
        for (int dd = 0; dd < 3; dd++) {
            int i2 = ty * 32 + i + dd - 1;
            bool iv = (i2 >= 0) && (i2 < L);
            if (iv && jv[dd]) {
                int rowi = (i2 & 31) * 32 + (i2 >> 5);
                s += T[(size_t)rowi * L + col[dd]];
            }
        }
        float vv = s * g_mmk[i * 32 + ty] * 10.0f;
        v[i] = vv;
        mx = fmaxf(mx, vv);
    }

    red[ty][tx] = mx; __syncthreads();
    #pragma unroll
    for (int s = 16; s > 0; s >>= 1) {
        if (ty < s) red[ty][tx] = fmaxf(red[ty][tx], red[ty + s][tx]);
        __syncthreads();
    }
    float m = red[0][tx];
    __syncthreads();

    float sum = 0.f;
    #pragma unroll
    for (int i = 0; i < 32; i++) {
        v[i] = expf(v[i] - m);
        sum += v[i];
    }
    red[ty][tx] = sum; __syncthreads();
    #pragma unroll
    for (int s = 16; s > 0; s >>= 1) {
        if (ty < s) red[ty][tx] += red[ty + s][tx];
        __syncthreads();
    }
    float inv = 1.0f / red[0][tx];
    __syncthreads();

    // write transposed: dst[p][q] fp16
    #pragma unroll
    for (int i = 0; i < 32; i++) {
        red[ty][tx] = v[i] * inv * g_mmk[i * 32 + ty];
        __syncthreads();
        dst[(size_t)(hf * 32 + ty) * L + i * 32 + tx] = __float2half(red[tx][ty]);
        __syncthreads();
    }
}

// ---- 10. build W fp16, N-major: g_Wh[b][n][q] ----
__global__ void k_buildWh(const float* __restrict__ b_in) {
    int idx = blockIdx.x * blockDim.x + threadIdx.x;
    if (idx >= NB*NCOLS*L) return;
    int q = idx & 1023;
    int n = (idx >> 10) & (NCOLS - 1);
    int bb = idx >> 21;
    int v = n & 3, u = (n >> 2) & 3, c = n >> 4;
    int qy = q >> 5, qx = q & 31;
    int by = 2 * qy + u - 1, bx = 2 * qx + v - 1;
    float val = 0.f;
    if (by >= 0 && by < 64 && bx >= 0 && bx < 64)
        val = b_in[((size_t)(bb * NC + c)) * 4096 + (size_t)by * 64 + bx];
    g_Wh[idx] = __float2half(val);
}

// =====================================================================
// GEMM2 via fp16 mma.sync m16n8k16 (2x MAC rate of tf32):
// OP[p,n] = sum_q attn[p,q] * W[q,n]
// A = g_attnh [M=1024 p][K=1024 q] row-major fp16
// B = g_Wh    [N=2048 n][K=1024 q] N-major fp16 (= col-major B, as
//     required by mma .col)
// 128x128 CTA tile, 128 threads / 4 warps (64x64 warp tile), BK=64
// (4 k16 steps per tile, 16 tiles), cp.async double buffer.
// smem rows: 64 data halves + 8 pad = 72 halves (36 words) -> bank
// (4*r8+cc), conflict-free fragment loads.
// =====================================================================
#define H_LDW 36                       // words per smem row
#define H_STAGE_W (2*128*H_LDW)        // words per stage (A + B tiles)

__global__ void __launch_bounds__(128, 2)
mma_gemm2h(const __half* __restrict__ Aall, const __half* __restrict__ Ball,
           float* __restrict__ Call) {
    extern __shared__ uint32_t smw[];
    const __half* A = Aall + (size_t)blockIdx.z * L * L;
    const __half* B = Ball + (size_t)blockIdx.z * (size_t)NCOLS * L;
    float* C = Call + (size_t)blockIdx.z * (size_t)L * NCOLS;
    const int bm = blockIdx.y * 128, bn = blockIdx.x * 128;
    const int tid = threadIdx.x;
    const int warp = tid >> 5, lane = tid & 31;
    const int wm = (warp & 1) << 6, wn = (warp >> 1) << 6;
    const int r8 = lane >> 2, cc = lane & 3;

    float acc[4][8][4];
    #pragma unroll
    for (int mi = 0; mi < 4; mi++)
      #pragma unroll
      for (int ni = 0; ni < 8; ni++)
        #pragma unroll
        for (int k = 0; k < 4; k++) acc[mi][ni][k] = 0.f;

    const __half* ag = A + (size_t)(bm + tid) * L;   // + kt*64
    const __half* bg = B + (size_t)(bn + tid) * L;   // + kt*64
    uint32_t smb = (uint32_t)__cvta_generic_to_shared(smw);

    // prologue: stage 0
    {
        uint32_t as_ = smb + (uint32_t)tid * 144u;              // tid*36 words
        uint32_t bs_ = smb + 128u * 144u + (uint32_t)tid * 144u;
        #pragma unroll
        for (int i = 0; i < 8; i++) {
            cp_async16(as_ + i * 16, ag + i * 8);
            cp_async16(bs_ + i * 16, bg + i * 8);
        }
        asm volatile("cp.async.commit_group;");
    }

    int buf = 0;
    for (int kt = 0; kt < 16; kt++) {
        if (kt + 1 < 16) {
            int nb = buf ^ 1;
            uint32_t sb = smb + (uint32_t)(nb * H_STAGE_W) * 4u;
            const __half* ag_ = ag + (kt + 1) * 64;
            const __half* bg_ = bg + (kt + 1) * 64;
            uint32_t as_ = sb + (uint32_t)tid * 144u;
            uint32_t bs_ = sb + 128u * 144u + (uint32_t)tid * 144u;
            #pragma unroll
            for (int i = 0; i < 8; i++) {
                cp_async16(as_ + i * 16, ag_ + i * 8);
                cp_async16(bs_ + i * 16, bg_ + i * 8);
            }
            asm volatile("cp.async.commit_group;");
            asm volatile("cp.async.wait_group 1;");
        } else {
            asm volatile("cp.async.wait_group 0;");
        }
        __syncthreads();

        const uint32_t* As = smw + buf * H_STAGE_W;
        const uint32_t* Bs = As + 128 * H_LDW;
        #pragma unroll
        for (int s = 0; s < 4; s++) {
            const int kw = s * 8;   // word offset of this k16 step
            uint32_t a[4][4], b[8][2];
            #pragma unroll
            for (int mi = 0; mi < 4; mi++) {
                const uint32_t* ap = As + (wm + mi * 16 + r8) * H_LDW + kw + cc;
                a[mi][0] = ap[0];
                a[mi][1] = ap[8 * H_LDW];
                a[mi][2] = ap[4];
                a[mi][3] = ap[8 * H_LDW + 4];
            }
            #pragma unroll
            for (int ni = 0; ni < 8; ni++) {
                const uint32_t* bp = Bs + (wn + ni * 8 + r8) * H_LDW + kw + cc;
                b[ni][0] = bp[0];
                b[ni][1] = bp[4];
            }
            #pragma unroll
            for (int mi = 0; mi < 4; mi++)
                #pragma unroll
                for (int ni = 0; ni < 8; ni++)
                    mma_f16(acc[mi][ni], a[mi], b[ni]);
        }
        __syncthreads();
        buf ^= 1;
    }

    #pragma unroll
    for (int mi = 0; mi < 4; mi++) {
        int row = bm + wm + mi * 16 + r8;
        #pragma unroll
        for (int ni = 0; ni < 8; ni++) {
            int col = bn + wn + ni * 8 + cc * 2;
            *(float2*)(C + (size_t)row * NCOLS + col) =
                make_float2(acc[mi][ni][0], acc[mi][ni][1]);
            *(float2*)(C + (size_t)(row + 8) * NCOLS + col) =
                make_float2(acc[mi][ni][2], acc[mi][ni][3]);
        }
    }
}

// ---- 12. overlap-add gather (deconv epilogue) ----
__global__ void k_gather(float* __restrict__ out) {
    int idx = blockIdx.x * blockDim.x + threadIdx.x;
    if (idx >= NB*NC*4096) return;
    int ox = idx & 63, oy = (idx >> 6) & 63, c = (idx >> 12) & 127, bb = idx >> 19;
    float s = 0.f;
    int ay = (oy + 1) & 1, ax = (ox + 1) & 1;
    #pragma unroll
    for (int uu = 0; uu < 2; uu++) {
        int u = ay + 2 * uu;
        int t = oy + 1 - u;
        if (t < 0) continue;
        int py = t >> 1;
        if (py >= HG) continue;
        #pragma unroll
        for (int vv = 0; vv < 2; vv++) {
            int v = ax + 2 * vv;
            int t2 = ox + 1 - v;
            if (t2 < 0) continue;
            int px = t2 >> 1;
            if (px >= HG) continue;
            s += g_OP[((size_t)bb * L + py * HG + px) * NCOLS + c * 16 + u * 4 + v];
        }
    }
    out[idx] = 0.25f * s;
}

extern "C" void kernel_launch(void* const* d_in, const int* in_sizes, int n_in,
                              void* d_out, int out_size) {
    (void)in_sizes; (void)n_in; (void)out_size;
    const float* f    = (const float*)d_in[0];
    const float* b    = (const float*)d_in[1];
    const float* mask = (const float*)d_in[2];
    float* out = (float*)d_out;

    float *p_fd, *p_bd, *p_corr, *p_OP;
    __half *p_attnh, *p_Wh;
    cudaGetSymbolAddress((void**)&p_fd,    g_fd);
    cudaGetSymbolAddress((void**)&p_bd,    g_bd);
    cudaGetSymbolAddress((void**)&p_corr,  g_corr);
    cudaGetSymbolAddress((void**)&p_attnh, g_attnh);
    cudaGetSymbolAddress((void**)&p_Wh,    g_Wh);
    cudaGetSymbolAddress((void**)&p_OP,    g_OP);

    const int g1_smem = 2 * G1_STAGE * 4;    // 69632 bytes
    const int g2_smem = 2 * H_STAGE_W * 4;   // 73728 bytes
    cudaFuncSetAttribute(mma_gemm1,  cudaFuncAttributeMaxDynamicSharedMemorySize, g1_smem);
    cudaFuncSetAttribute(mma_gemm2h, cudaFuncAttributeMaxDynamicSharedMemorySize, g2_smem);

    k_down<<<(NB*NC*L + 255) / 256, 256>>>(f, b);
    k_ssq<<<(NB*L + 255) / 256, 256>>>();
    k_rnorm<<<(NB*L + 255) / 256, 256>>>();

    // GEMM1: corr[q,p] (M=N=1024, K=128) — 3xTF32 mma.sync
    {
        dim3 grid(L / 128, L / 128, NB);
        mma_gemm1<<<grid, 128, g1_smem>>>(p_bd, p_fd, p_corr);
    }

    // fused scores + fuse1
    {
        dim3 grid(32, 32, NB);
        dim3 blk(32, 8);
        k_scores_fuse1<<<grid, blk>>>();
    }
    k_mm<<<(L + 255) / 256, 256>>>(mask);
    {
        dim3 grid(32, NB);
        dim3 blk(32, 32);
        k_fuse2_softmax<<<grid, blk>>>();
    }
    k_buildWh<<<(NB*NCOLS*L + 255) / 256, 256>>>(b);

    // GEMM2: OP[p,n] (M=1024, N=2048, K=1024) — fp16 m16n8k16 MMA
    {
        dim3 grid(NCOLS / 128, L / 128, NB);
        mma_gemm2h<<<grid, 128, g2_smem>>>(p_attnh, p_Wh, p_OP);
    }

    k_gather<<<(NB*NC*4096 + 255) / 256, 256>>>(out);
}

// round 13
// speedup vs baseline: 1.4326x; 1.0562x over previous
#include <cuda_runtime.h>
#include <cuda_fp16.h>
#include <math.h>
#include <stdint.h>

#define NB 2
#define NC 128
#define HG 32
#define L 1024
#define NCOLS 2048   // NC * 16
#define KP 64        // NC/2 channel pairs

// ---- scratch (device globals; no allocation allowed) ----
__device__ float g_bd[NB*NC*L];          // fp32 bd (for ssq)
__device__ uint32_t g_bdh[NB*KP*L];      // bd hi half2 [b][kp][m]
__device__ uint32_t g_bdl[NB*KP*L];      // bd lo half2
__device__ uint32_t g_fdh[NB*KP*L];      // fd hi half2
__device__ uint32_t g_fdl[NB*KP*L];      // fd lo half2
__device__ float g_ssq[NB*L];
__device__ float g_rnorm[NB*L];
__device__ float g_corr[NB*L*L];         // corr[q][p]
__device__ float g_t1[NB*L*L];           // fused scores+fuse1 output [q][p]
__device__ float g_mmk[L];
__device__ __half g_attnh[NB*L*L];       // attn [b][p][q], fp16
__device__ __half g_Wh[NB*NCOLS*L];      // W [b][n][q], fp16
__device__ float g_OP[NB*NCOLS*L];       // deconv GEMM output [b][n][p]  (TRANSPOSED)

// ---- helpers ----
__device__ __forceinline__ void cp_async16(uint32_t s, const void* g) {
    asm volatile("cp.async.cg.shared.global [%0], [%1], 16;" :: "r"(s), "l"(g));
}
__device__ __forceinline__ void mma_f16(float* c, const uint32_t* a, const uint32_t* b) {
    asm volatile(
        "mma.sync.aligned.m16n8k16.row.col.f32.f16.f16.f32 "
        "{%0,%1,%2,%3}, {%4,%5,%6,%7}, {%8,%9}, {%0,%1,%2,%3};"
        : "+f"(c[0]), "+f"(c[1]), "+f"(c[2]), "+f"(c[3])
        : "r"(a[0]), "r"(a[1]), "r"(a[2]), "r"(a[3]), "r"(b[0]), "r"(b[1]));
}
__device__ __forceinline__ uint32_t pack_h2(__half a, __half b) {
    return (uint32_t)__half_as_ushort(a) | ((uint32_t)__half_as_ushort(b) << 16);
}

// ---- 1. downsample by 2 + fp16 hi/lo split pack (channel pairs) ----
__global__ void k_down_split(const float* __restrict__ f, const float* __restrict__ b) {
    int idx = blockIdx.x * blockDim.x + threadIdx.x;
    if (idx >= NB*KP*L) return;
    int m = idx & 1023;
    int kp = (idx >> 10) & (KP - 1);
    int bb = idx >> 16;
    int x = m & 31, y = m >> 5;
    int c0 = 2 * kp;
    size_t base0 = ((size_t)(bb * NC + c0)) * 4096 + (size_t)(2*y) * 64 + 2*x;
    size_t base1 = base0 + 4096;
    float f0 = f[base0], f1 = f[base1];
    float b0 = b[base0], b1 = b[base1];

    g_bd[(size_t)(bb * NC + c0) * L + m] = b0;
    g_bd[(size_t)(bb * NC + c0 + 1) * L + m] = b1;

    __half bh0 = __float2half(b0), bh1 = __float2half(b1);
    __half bl0 = __float2half(b0 - __half2float(bh0));
    __half bl1 = __float2half(b1 - __half2float(bh1));
    __half fh0 = __float2half(f0), fh1 = __float2half(f1);
    __half fl0 = __float2half(f0 - __half2float(fh0));
    __half fl1 = __float2half(f1 - __half2float(fh1));

    size_t o = (size_t)bb * KP * L + (size_t)kp * L + m;
    g_bdh[o] = pack_h2(bh0, bh1);
    g_bdl[o] = pack_h2(bl0, bl1);
    g_fdh[o] = pack_h2(fh0, fh1);
    g_fdl[o] = pack_h2(fl0, fl1);
}

// ---- 2. per-pixel sum over c of bd^2 ----
__global__ void k_ssq() {
    int idx = blockIdx.x * blockDim.x + threadIdx.x;
    if (idx >= NB*L) return;
    int bb = idx >> 10, q = idx & 1023;
    float s = 0.f;
    const float* p = g_bd + (size_t)bb * NC * L + q;
    #pragma unroll 8
    for (int c = 0; c < NC; c++) { float v = p[(size_t)c * L]; s += v * v; }
    g_ssq[idx] = s;
}

// ---- 3. patch inverse norms (3x3, zero pad) ----
__global__ void k_rnorm() {
    int idx = blockIdx.x * blockDim.x + threadIdx.x;
    if (idx >= NB*L) return;
    int bb = idx >> 10, q = idx & 1023;
    int qy = q >> 5, qx = q & 31;
    float s = 1152.0f * 0.0001f;
    for (int dy = -1; dy <= 1; dy++)
      for (int dx = -1; dx <= 1; dx++) {
        int y = qy + dy, x = qx + dx;
        if (y >= 0 && y < HG && x >= 0 && x < HG) s += g_ssq[bb*L + y*HG + x];
      }
    g_rnorm[idx] = 1.0f / sqrtf(s);
}

// =====================================================================
// GEMM1 via fp16-split m16n8k16 (near-fp32):
// corr[q,p] = sum_c bd[c,q]*fd[c,p] = (hi_a+lo_a)·(hi_b+lo_b) dropping
// lo·lo.  A/B stored as half2-per-kp arrays [kp][m] K-major.
// 128x128 CTA tile, 128 threads / 4 warps (64x64 warp tile), 16 kp per
// stage (BK=32 channels), 4 stages, cp.async double buffer.
// =====================================================================
#define S_LD 136                       // u32 per smem row
#define G1_TILE (16*S_LD)              // words per tile (16 kp x 128 m)
#define G1_STAGE (4*G1_TILE)           // Ahi,Alo,Bhi,Blo

__global__ void __launch_bounds__(128, 2)
mma_gemm1h(const uint32_t* __restrict__ Ah, const uint32_t* __restrict__ Al,
           const uint32_t* __restrict__ Bh, const uint32_t* __restrict__ Bl,
           float* __restrict__ Call) {
    extern __shared__ uint32_t smw[];
    const size_t bofs = (size_t)blockIdx.z * KP * L;
    float* C = Call + (size_t)blockIdx.z * (size_t)L * L;
    const int bm = blockIdx.y * 128, bn = blockIdx.x * 128;
    const int tid = threadIdx.x;
    const int warp = tid >> 5, lane = tid & 31;
    const int wm = (warp & 1) << 6, wn = (warp >> 1) << 6;
    const int r8 = lane >> 2, cc = lane & 3;

    float acc[4][8][4];
    #pragma unroll
    for (int mi = 0; mi < 4; mi++)
      #pragma unroll
      for (int ni = 0; ni < 8; ni++)
        #pragma unroll
        for (int k = 0; k < 4; k++) acc[mi][ni][k] = 0.f;

    const int lr = tid >> 3;                 // row 0..15
    const int lc = (tid & 7) * 16;           // u32 col base (4 chunks of 4)
    uint32_t smb = (uint32_t)__cvta_generic_to_shared(smw);

    // per-stage loader
    auto load_stage = [&](int buf, int kt) {
        uint32_t sb = smb + (uint32_t)(buf * G1_STAGE) * 4u;
        size_t gro = bofs + (size_t)(kt * 16 + lr) * L;
        const uint32_t* s0 = Ah + gro + bm + lc;
        const uint32_t* s1 = Al + gro + bm + lc;
        const uint32_t* s2 = Bh + gro + bn + lc;
        const uint32_t* s3 = Bl + gro + bn + lc;
        uint32_t d = sb + (uint32_t)(lr * S_LD + lc) * 4u;
        #pragma unroll
        for (int j = 0; j < 4; j++) {
            cp_async16(d + j * 16,                      s0 + j * 4);
            cp_async16(d + j * 16 + G1_TILE * 4u,       s1 + j * 4);
            cp_async16(d + j * 16 + 2u * G1_TILE * 4u,  s2 + j * 4);
            cp_async16(d + j * 16 + 3u * G1_TILE * 4u,  s3 + j * 4);
        }
        asm volatile("cp.async.commit_group;");
    };

    load_stage(0, 0);

    const int NKT = 4;
    int buf = 0;
    for (int kt = 0; kt < NKT; kt++) {
        if (kt + 1 < NKT) {
            load_stage(buf ^ 1, kt + 1);
            asm volatile("cp.async.wait_group 1;");
        } else {
            asm volatile("cp.async.wait_group 0;");
        }
        __syncthreads();

        const uint32_t* Ahi = smw + buf * G1_STAGE;
        const uint32_t* Alo = Ahi + G1_TILE;
        const uint32_t* Bhi = Ahi + 2 * G1_TILE;
        const uint32_t* Blo = Ahi + 3 * G1_TILE;
        #pragma unroll
        for (int s = 0; s < 2; s++) {
            const int kpb = s * 8;
            uint32_t ah[4][4], al[4][4], bh[8][2], bl[8][2];
            #pragma unroll
            for (int mi = 0; mi < 4; mi++) {
                int mo = wm + mi * 16 + r8;
                const uint32_t* p0 = Ahi + (kpb + cc) * S_LD + mo;
                ah[mi][0] = p0[0];
                ah[mi][1] = p0[8];
                ah[mi][2] = p0[4 * S_LD];
                ah[mi][3] = p0[4 * S_LD + 8];
                const uint32_t* p1 = Alo + (kpb + cc) * S_LD + mo;
                al[mi][0] = p1[0];
                al[mi][1] = p1[8];
                al[mi][2] = p1[4 * S_LD];
                al[mi][3] = p1[4 * S_LD + 8];
            }
            #pragma unroll
            for (int ni = 0; ni < 8; ni++) {
                int no = wn + ni * 8 + r8;
                const uint32_t* p0 = Bhi + (kpb + cc) * S_LD + no;
                bh[ni][0] = p0[0];
                bh[ni][1] = p0[4 * S_LD];
                const uint32_t* p1 = Blo + (kpb + cc) * S_LD + no;
                bl[ni][0] = p1[0];
                bl[ni][1] = p1[4 * S_LD];
            }
            #pragma unroll
            for (int mi = 0; mi < 4; mi++)
                #pragma unroll
                for (int ni = 0; ni < 8; ni++) {
                    mma_f16(acc[mi][ni], ah[mi], bh[ni]);
                    mma_f16(acc[mi][ni], ah[mi], bl[ni]);
                    mma_f16(acc[mi][ni], al[mi], bh[ni]);
                }
        }
        __syncthreads();
        buf ^= 1;
    }

    #pragma unroll
    for (int mi = 0; mi < 4; mi++) {
        int r = bm + wm + mi * 16 + r8;
        #pragma unroll
        for (int ni = 0; ni < 8; ni++) {
            int col = bn + wn + ni * 8 + cc * 2;
            *(float2*)(C + (size_t)r * L + col) =
                make_float2(acc[mi][ni][0], acc[mi][ni][1]);
            *(float2*)(C + (size_t)(r + 8) * L + col) =
                make_float2(acc[mi][ni][2], acc[mi][ni][3]);
        }
    }
}

// =====================================================================
// 5+6 fused: scores (9-tap + normalize) + fuse1 (diagonal 3-tap),
// writing g_t1 directly.  Block (32,8); output tile 32(q) x 32(p).
// =====================================================================
__global__ void __launch_bounds__(256) k_scores_fuse1() {
    __shared__ float ssc[34][35];
    const int bb = blockIdx.z;
    const int p0 = blockIdx.x * 32, q0 = blockIdx.y * 32;
    const float* M = g_corr + (size_t)bb * L * L;
    const float* rn = g_rnorm + bb * L;
    float* dst = g_t1 + (size_t)bb * L * L;
    const int tid = threadIdx.y * 32 + threadIdx.x;

    for (int idx = tid; idx < 34 * 34; idx += 256) {
        int a = idx / 34, b = idx - a * 34;
        int q = q0 - 1 + a, p = p0 - 1 + b;
        float s = 0.f;
        if (q >= 0 && q < L && p >= 0 && p < L) {
            int qy = q >> 5, qx = q & 31, py = p >> 5, px = p & 31;
            #pragma unroll
            for (int dy = -1; dy <= 1; dy++) {
                int qy2 = qy + dy, py2 = py + dy;
                if (qy2 < 0 || qy2 >= HG || py2 < 0 || py2 >= HG) continue;
                #pragma unroll
                for (int dx = -1; dx <= 1; dx++) {
                    int qx2 = qx + dx, px2 = px + dx;
                    if (qx2 < 0 || qx2 >= HG || px2 < 0 || px2 >= HG) continue;
                    s += M[(size_t)(qy2 * HG + qx2) * L + (py2 * HG + px2)];
                }
            }
            s *= rn[q];
        }
        ssc[a][b] = s;
    }
    __syncthreads();

    int tx = threadIdx.x, ty = threadIdx.y;
    #pragma unroll
    for (int r = 0; r < 4; r++) {
        int a = ty + 8 * r + 1, b = tx + 1;
        float s = ssc[a][b] + ssc[a - 1][b - 1] + ssc[a + 1][b + 1];
        dst[(size_t)(q0 + ty + 8 * r) * L + p0 + tx] = s;
    }
}

// ---- 8. mask gate (batch 0 of mask) ----
__global__ void k_mm(const float* __restrict__ mask) {
    int q = blockIdx.x * blockDim.x + threadIdx.x;
    if (q >= L) return;
    int qy = q >> 5, qx = q & 31;
    float s = 0.f;
    for (int dy = -1; dy <= 1; dy++)
      for (int dx = -1; dx <= 1; dx++) {
        int y = qy + dy, x = qx + dx;
        if (y >= 0 && y < HG && x >= 0 && x < HG)
            s += mask[(size_t)(8 * y) * 256 + 8 * x];
      }
    g_mmk[q] = (s == 0.0f) ? 1.0f : 0.0f;
}

// =====================================================================
// 7+9 fused: fuse pass 2 + softmax over q, writing attn TRANSPOSED
// [p][q] as fp16.  Block (32,32); one block per (hf, batch).
// =====================================================================
__global__ void __launch_bounds__(1024) k_fuse2_softmax() {
    int bb = blockIdx.y, hf = blockIdx.x;
    int tx = threadIdx.x, ty = threadIdx.y;
    const float* T = g_t1 + (size_t)bb * L * L;
    __half* dst = g_attnh + (size_t)bb * L * L;
    __shared__ float red[32][33];

    int col[3]; bool jv[3];
    #pragma unroll
    for (int dd = 0; dd < 3; dd++) {
        int j2 = tx * 32 + hf + dd - 1;
        jv[dd] = (j2 >= 0) && (j2 < L);
        int jj = jv[dd] ? j2 : 0;
        col[dd] = (jj & 31) * 32 + (jj >> 5);
    }

    float v[32];
    float mx = -1e30f;
    #pragma unroll
    for (int i = 0; i < 32; i++) {
        float s = 0.f;
        #pragma unroll
        for (int dd = 0; dd < 3; dd++) {
            int i2 = ty * 32 + i + dd - 1;
            bool iv = (i2 >= 0) && (i2 < L);
            if (iv && jv[dd]) {
                int rowi = (i2 & 31) * 32 + (i2 >> 5);
                s += T[(size_t)rowi * L + col[dd]];
            }
        }
        float vv = s * g_mmk[i * 32 + ty] * 10.0f;
        v[i] = vv;
        mx = fmaxf(mx, vv);
    }

    red[ty][tx] = mx; __syncthreads();
    #pragma unroll
    for (int s = 16; s > 0; s >>= 1) {
        if (ty < s) red[ty][tx] = fmaxf(red[ty][tx], red[ty + s][tx]);
        __syncthreads();
    }
    float m = red[0][tx];
    __syncthreads();

    float sum = 0.f;
    #pragma unroll
    for (int i = 0; i < 32; i++) {
        v[i] = expf(v[i] - m);
        sum += v[i];
    }
    red[ty][tx] = sum; __syncthreads();
    #pragma unroll
    for (int s = 16; s > 0; s >>= 1) {
        if (ty < s) red[ty][tx] += red[ty + s][tx];
        __syncthreads();
    }
    float inv = 1.0f / red[0][tx];
    __syncthreads();

    // write transposed: dst[p][q] fp16
    #pragma unroll
    for (int i = 0; i < 32; i++) {
        red[ty][tx] = v[i] * inv * g_mmk[i * 32 + ty];
        __syncthreads();
        dst[(size_t)(hf * 32 + ty) * L + i * 32 + tx] = __float2half(red[tx][ty]);
        __syncthreads();
    }
}

// ---- 10. build W fp16, N-major: g_Wh[b][n][q] ----
__global__ void k_buildWh(const float* __restrict__ b_in) {
    int idx = blockIdx.x * blockDim.x + threadIdx.x;
    if (idx >= NB*NCOLS*L) return;
    int q = idx & 1023;
    int n = (idx >> 10) & (NCOLS - 1);
    int bb = idx >> 21;
    int v = n & 3, u = (n >> 2) & 3, c = n >> 4;
    int qy = q >> 5, qx = q & 31;
    int by = 2 * qy + u - 1, bx = 2 * qx + v - 1;
    float val = 0.f;
    if (by >= 0 && by < 64 && bx >= 0 && bx < 64)
        val = b_in[((size_t)(bb * NC + c)) * 4096 + (size_t)by * 64 + bx];
    g_Wh[idx] = __float2half(val);
}

// =====================================================================
// GEMM2 via fp16 m16n8k16, TRANSPOSED output:
// OP[n,p] = sum_q W[n,q] * attn[p,q]
// A = g_Wh    [M=2048 n][K=1024 q] row-major fp16
// B = g_attnh [N=1024 p][K=1024 q] col-major-B (N-major) fp16
// C = g_OP [n][p], row stride L.  128x128 CTA tile, 4 warps, BK=64,
// cp.async double buffer.
// =====================================================================
#define H_LDW 36                       // words per smem row
#define H_STAGE_W (2*128*H_LDW)

__global__ void __launch_bounds__(128, 2)
mma_gemm2h(const __half* __restrict__ Aall, const __half* __restrict__ Ball,
           float* __restrict__ Call) {
    extern __shared__ uint32_t smw[];
    const __half* A = Aall + (size_t)blockIdx.z * (size_t)NCOLS * L;
    const __half* B = Ball + (size_t)blockIdx.z * (size_t)L * L;
    float* C = Call + (size_t)blockIdx.z * (size_t)NCOLS * L;
    const int bm = blockIdx.y * 128, bn = blockIdx.x * 128;
    const int tid = threadIdx.x;
    const int warp = tid >> 5, lane = tid & 31;
    const int wm = (warp & 1) << 6, wn = (warp >> 1) << 6;
    const int r8 = lane >> 2, cc = lane & 3;

    float acc[4][8][4];
    #pragma unroll
    for (int mi = 0; mi < 4; mi++)
      #pragma unroll
      for (int ni = 0; ni < 8; ni++)
        #pragma unroll
        for (int k = 0; k < 4; k++) acc[mi][ni][k] = 0.f;

    const __half* ag = A + (size_t)(bm + tid) * L;
    const __half* bg = B + (size_t)(bn + tid) * L;
    uint32_t smb = (uint32_t)__cvta_generic_to_shared(smw);

    {
        uint32_t as_ = smb + (uint32_t)tid * 144u;
        uint32_t bs_ = smb + 128u * 144u + (uint32_t)tid * 144u;
        #pragma unroll
        for (int i = 0; i < 8; i++) {
            cp_async16(as_ + i * 16, ag + i * 8);
            cp_async16(bs_ + i * 16, bg + i * 8);
        }
        asm volatile("cp.async.commit_group;");
    }

    int buf = 0;
    for (int kt = 0; kt < 16; kt++) {
        if (kt + 1 < 16) {
            int nb = buf ^ 1;
            uint32_t sb = smb + (uint32_t)(nb * H_STAGE_W) * 4u;
            const __half* ag_ = ag + (kt + 1) * 64;
            const __half* bg_ = bg + (kt + 1) * 64;
            uint32_t as_ = sb + (uint32_t)tid * 144u;
            uint32_t bs_ = sb + 128u * 144u + (uint32_t)tid * 144u;
            #pragma unroll
            for (int i = 0; i < 8; i++) {
                cp_async16(as_ + i * 16, ag_ + i * 8);
                cp_async16(bs_ + i * 16, bg_ + i * 8);
            }
            asm volatile("cp.async.commit_group;");
            asm volatile("cp.async.wait_group 1;");
        } else {
            asm volatile("cp.async.wait_group 0;");
        }
        __syncthreads();

        const uint32_t* As = smw + buf * H_STAGE_W;
        const uint32_t* Bs = As + 128 * H_LDW;
        #pragma unroll
        for (int s = 0; s < 4; s++) {
            const int kw = s * 8;
            uint32_t a[4][4], b[8][2];
            #pragma unroll
            for (int mi = 0; mi < 4; mi++) {
                const uint32_t* ap = As + (wm + mi * 16 + r8) * H_LDW + kw + cc;
                a[mi][0] = ap[0];
                a[mi][1] = ap[8 * H_LDW];
                a[mi][2] = ap[4];
                a[mi][3] = ap[8 * H_LDW + 4];
            }
            #pragma unroll
            for (int ni = 0; ni < 8; ni++) {
                const uint32_t* bp = Bs + (wn + ni * 8 + r8) * H_LDW + kw + cc;
                b[ni][0] = bp[0];
                b[ni][1] = bp[4];
            }
            #pragma unroll
            for (int mi = 0; mi < 4; mi++)
                #pragma unroll
                for (int ni = 0; ni < 8; ni++)
                    mma_f16(acc[mi][ni], a[mi], b[ni]);
        }
        __syncthreads();
        buf ^= 1;
    }

    #pragma unroll
    for (int mi = 0; mi < 4; mi++) {
        int row = bm + wm + mi * 16 + r8;      // n index
        #pragma unroll
        for (int ni = 0; ni < 8; ni++) {
            int col = bn + wn + ni * 8 + cc * 2;   // p index
            *(float2*)(C + (size_t)row * L + col) =
                make_float2(acc[mi][ni][0], acc[mi][ni][1]);
            *(float2*)(C + (size_t)(row + 8) * L + col) =
                make_float2(acc[mi][ni][2], acc[mi][ni][3]);
        }
    }
}

// ---- 12. overlap-add gather (deconv epilogue); OP is [b][n][p] ----
__global__ void k_gather(float* __restrict__ out) {
    int idx = blockIdx.x * blockDim.x + threadIdx.x;
    if (idx >= NB*NC*4096) return;
    int ox = idx & 63, oy = (idx >> 6) & 63, c = (idx >> 12) & 127, bb = idx >> 19;
    float s = 0.f;
    int ay = (oy + 1) & 1, ax = (ox + 1) & 1;
    const float* OPb = g_OP + (size_t)bb * NCOLS * L;
    #pragma unroll
    for (int uu = 0; uu < 2; uu++) {
        int u = ay + 2 * uu;
        int t = oy + 1 - u;
        if (t < 0) continue;
        int py = t >> 1;
        if (py >= HG) continue;
        #pragma unroll
        for (int vv = 0; vv < 2; vv++) {
            int v = ax + 2 * vv;
            int t2 = ox + 1 - v;
            if (t2 < 0) continue;
            int px = t2 >> 1;
            if (px >= HG) continue;
            s += OPb[(size_t)(c * 16 + u * 4 + v) * L + py * HG + px];
        }
    }
    out[idx] = 0.25f * s;
}

extern "C" void kernel_launch(void* const* d_in, const int* in_sizes, int n_in,
                              void* d_out, int out_size) {
    (void)in_sizes; (void)n_in; (void)out_size;
    const float* f    = (const float*)d_in[0];
    const float* b    = (const float*)d_in[1];
    const float* mask = (const float*)d_in[2];
    float* out = (float*)d_out;

    float *p_corr, *p_OP;
    uint32_t *p_bdh, *p_bdl, *p_fdh, *p_fdl;
    __half *p_attnh, *p_Wh;
    cudaGetSymbolAddress((void**)&p_corr,  g_corr);
    cudaGetSymbolAddress((void**)&p_bdh,   g_bdh);
    cudaGetSymbolAddress((void**)&p_bdl,   g_bdl);
    cudaGetSymbolAddress((void**)&p_fdh,   g_fdh);
    cudaGetSymbolAddress((void**)&p_fdl,   g_fdl);
    cudaGetSymbolAddress((void**)&p_attnh, g_attnh);
    cudaGetSymbolAddress((void**)&p_Wh,    g_Wh);
    cudaGetSymbolAddress((void**)&p_OP,    g_OP);

    const int g1_smem = 2 * G1_STAGE * 4;    // 69632 bytes
    const int g2_smem = 2 * H_STAGE_W * 4;   // 73728 bytes
    cudaFuncSetAttribute(mma_gemm1h, cudaFuncAttributeMaxDynamicSharedMemorySize, g1_smem);
    cudaFuncSetAttribute(mma_gemm2h, cudaFuncAttributeMaxDynamicSharedMemorySize, g2_smem);

    k_down_split<<<(NB*KP*L + 255) / 256, 256>>>(f, b);
    k_ssq<<<(NB*L + 255) / 256, 256>>>();
    k_rnorm<<<(NB*L + 255) / 256, 256>>>();

    // GEMM1: corr[q,p] (M=N=1024, K=128 channels) — 3x fp16-split MMA
    {
        dim3 grid(L / 128, L / 128, NB);
        mma_gemm1h<<<grid, 128, g1_smem>>>(p_bdh, p_bdl, p_fdh, p_fdl, p_corr);
    }

    // fused scores + fuse1
    {
        dim3 grid(32, 32, NB);
        dim3 blk(32, 8);
        k_scores_fuse1<<<grid, blk>>>();
    }
    k_mm<<<(L + 255) / 256, 256>>>(mask);
    {
        dim3 grid(32, NB);
        dim3 blk(32, 32);
        k_fuse2_softmax<<<grid, blk>>>();
    }
    k_buildWh<<<(NB*NCOLS*L + 255) / 256, 256>>>(b);

    // GEMM2: OP[n,p] (M=2048, N=1024, K=1024) — fp16 MMA, transposed out
    {
        dim3 grid(L / 128, NCOLS / 128, NB);
        mma_gemm2h<<<grid, 128, g2_smem>>>(p_Wh, p_attnh, p_OP);
    }

    k_gather<<<(NB*NC*4096 + 255) / 256, 256>>>(out);
}

// round 14
// speedup vs baseline: 1.5076x; 1.0523x over previous
#include <cuda_runtime.h>
#include <cuda_fp16.h>
#include <math.h>
#include <stdint.h>

#define NB 2
#define NC 128
#define HG 32
#define L 1024
#define NCOLS 2048   // NC * 16
#define KP 64        // NC/2 channel pairs

// ---- scratch (device globals; no allocation allowed) ----
__device__ uint32_t g_bdh[NB*KP*L];      // bd hi half2 [b][kp][m]
__device__ uint32_t g_bdl[NB*KP*L];      // bd lo half2
__device__ uint32_t g_fdh[NB*KP*L];      // fd hi half2
__device__ uint32_t g_fdl[NB*KP*L];      // fd lo half2
__device__ float g_ssq[NB*L];
__device__ float g_rnorm[NB*L];
__device__ float g_corr[NB*L*L];         // corr[q][p]
__device__ float g_t1[NB*L*L];           // fused scores+fuse1 output [q][p]
__device__ float g_mmk[L];
__device__ __half g_attnh[NB*L*L];       // attn [b][p][q], fp16
__device__ __half g_Wh[NB*NCOLS*L];      // W [b][n][q], fp16
__device__ float g_OP[NB*NCOLS*L];       // deconv GEMM output [b][n][p] (transposed)

// ---- helpers ----
__device__ __forceinline__ void cp_async16(uint32_t s, const void* g) {
    asm volatile("cp.async.cg.shared.global [%0], [%1], 16;" :: "r"(s), "l"(g));
}
__device__ __forceinline__ void mma_f16(float* c, const uint32_t* a, const uint32_t* b) {
    asm volatile(
        "mma.sync.aligned.m16n8k16.row.col.f32.f16.f16.f32 "
        "{%0,%1,%2,%3}, {%4,%5,%6,%7}, {%8,%9}, {%0,%1,%2,%3};"
        : "+f"(c[0]), "+f"(c[1]), "+f"(c[2]), "+f"(c[3])
        : "r"(a[0]), "r"(a[1]), "r"(a[2]), "r"(a[3]), "r"(b[0]), "r"(b[1]));
}
__device__ __forceinline__ uint32_t pack_h2(__half a, __half b) {
    return (uint32_t)__half_as_ushort(a) | ((uint32_t)__half_as_ushort(b) << 16);
}
__device__ __forceinline__ float2 h2_to_f2(uint32_t u) {
    __half2 h = *reinterpret_cast<__half2*>(&u);
    return __half22float2(h);
}

// ---- 1. downsample by 2 + fp16 hi/lo split pack (channel pairs) ----
__global__ void k_down_split(const float* __restrict__ f, const float* __restrict__ b) {
    int idx = blockIdx.x * blockDim.x + threadIdx.x;
    if (idx >= NB*KP*L) return;
    int m = idx & 1023;
    int kp = (idx >> 10) & (KP - 1);
    int bb = idx >> 16;
    int x = m & 31, y = m >> 5;
    int c0 = 2 * kp;
    size_t base0 = ((size_t)(bb * NC + c0)) * 4096 + (size_t)(2*y) * 64 + 2*x;
    size_t base1 = base0 + 4096;
    float f0 = f[base0], f1 = f[base1];
    float b0 = b[base0], b1 = b[base1];

    __half bh0 = __float2half(b0), bh1 = __float2half(b1);
    __half bl0 = __float2half(b0 - __half2float(bh0));
    __half bl1 = __float2half(b1 - __half2float(bh1));
    __half fh0 = __float2half(f0), fh1 = __float2half(f1);
    __half fl0 = __float2half(f0 - __half2float(fh0));
    __half fl1 = __float2half(f1 - __half2float(fh1));

    size_t o = (size_t)bb * KP * L + (size_t)kp * L + m;
    g_bdh[o] = pack_h2(bh0, bh1);
    g_bdl[o] = pack_h2(bl0, bl1);
    g_fdh[o] = pack_h2(fh0, fh1);
    g_fdl[o] = pack_h2(fl0, fl1);
}

// ---- 2. per-pixel sum over c of bd^2 (reconstruct from hi+lo) ----
__global__ void k_ssq() {
    int idx = blockIdx.x * blockDim.x + threadIdx.x;
    if (idx >= NB*L) return;
    int bb = idx >> 10, q = idx & 1023;
    const uint32_t* ph = g_bdh + (size_t)bb * KP * L + q;
    const uint32_t* pl = g_bdl + (size_t)bb * KP * L + q;
    float s = 0.f;
    #pragma unroll 8
    for (int kp = 0; kp < KP; kp++) {
        float2 h = h2_to_f2(ph[(size_t)kp * L]);
        float2 l = h2_to_f2(pl[(size_t)kp * L]);
        float v0 = h.x + l.x, v1 = h.y + l.y;
        s += v0 * v0 + v1 * v1;
    }
    g_ssq[idx] = s;
}

// ---- 3. patch inverse norms (3x3, zero pad) ----
__global__ void k_rnorm() {
    int idx = blockIdx.x * blockDim.x + threadIdx.x;
    if (idx >= NB*L) return;
    int bb = idx >> 10, q = idx & 1023;
    int qy = q >> 5, qx = q & 31;
    float s = 1152.0f * 0.0001f;
    for (int dy = -1; dy <= 1; dy++)
      for (int dx = -1; dx <= 1; dx++) {
        int y = qy + dy, x = qx + dx;
        if (y >= 0 && y < HG && x >= 0 && x < HG) s += g_ssq[bb*L + y*HG + x];
      }
    g_rnorm[idx] = 1.0f / sqrtf(s);
}

// =====================================================================
// GEMM1 via fp16-split m16n8k16 (near-fp32), 3-stage cp.async pipeline:
// corr[q,p] = sum_c bd[c,q]*fd[c,p], dropping lo·lo.
// 128x128 CTA tile, 128 threads / 4 warps (64x64 warp tile), 16 kp
// (BK=32 channels) per stage, 4 k-tiles.
// =====================================================================
#define S_LD 136                       // u32 per smem row
#define G1_TILE (16*S_LD)              // words per tile (16 kp x 128 m)
#define G1_STAGE (4*G1_TILE)           // Ahi,Alo,Bhi,Blo

__global__ void __launch_bounds__(128, 2)
mma_gemm1h(const uint32_t* __restrict__ Ah, const uint32_t* __restrict__ Al,
           const uint32_t* __restrict__ Bh, const uint32_t* __restrict__ Bl,
           float* __restrict__ Call) {
    extern __shared__ uint32_t smw[];
    const size_t bofs = (size_t)blockIdx.z * KP * L;
    float* C = Call + (size_t)blockIdx.z * (size_t)L * L;
    const int bm = blockIdx.y * 128, bn = blockIdx.x * 128;
    const int tid = threadIdx.x;
    const int warp = tid >> 5, lane = tid & 31;
    const int wm = (warp & 1) << 6, wn = (warp >> 1) << 6;
    const int r8 = lane >> 2, cc = lane & 3;

    float acc[4][8][4];
    #pragma unroll
    for (int mi = 0; mi < 4; mi++)
      #pragma unroll
      for (int ni = 0; ni < 8; ni++)
        #pragma unroll
        for (int k = 0; k < 4; k++) acc[mi][ni][k] = 0.f;

    const int lr = tid >> 3;                 // row 0..15
    const int lc = (tid & 7) * 16;           // u32 col base
    uint32_t smb = (uint32_t)__cvta_generic_to_shared(smw);

    auto load_stage = [&](int buf, int kt) {
        uint32_t sb = smb + (uint32_t)(buf * G1_STAGE) * 4u;
        size_t gro = bofs + (size_t)(kt * 16 + lr) * L;
        const uint32_t* s0 = Ah + gro + bm + lc;
        const uint32_t* s1 = Al + gro + bm + lc;
        const uint32_t* s2 = Bh + gro + bn + lc;
        const uint32_t* s3 = Bl + gro + bn + lc;
        uint32_t d = sb + (uint32_t)(lr * S_LD + lc) * 4u;
        #pragma unroll
        for (int j = 0; j < 4; j++) {
            cp_async16(d + j * 16,                      s0 + j * 4);
            cp_async16(d + j * 16 + G1_TILE * 4u,       s1 + j * 4);
            cp_async16(d + j * 16 + 2u * G1_TILE * 4u,  s2 + j * 4);
            cp_async16(d + j * 16 + 3u * G1_TILE * 4u,  s3 + j * 4);
        }
        asm volatile("cp.async.commit_group;");
    };

    load_stage(0, 0);
    load_stage(1, 1);

    const int NKT = 4;
    for (int kt = 0; kt < NKT; kt++) {
        if (kt + 2 < NKT) {
            load_stage((kt + 2) % 3, kt + 2);
            asm volatile("cp.async.wait_group 2;");
        } else if (kt == NKT - 2) {
            asm volatile("cp.async.wait_group 1;");
        } else {
            asm volatile("cp.async.wait_group 0;");
        }
        __syncthreads();

        const uint32_t* Ahi = smw + (kt % 3) * G1_STAGE;
        const uint32_t* Alo = Ahi + G1_TILE;
        const uint32_t* Bhi = Ahi + 2 * G1_TILE;
        const uint32_t* Blo = Ahi + 3 * G1_TILE;
        #pragma unroll
        for (int s = 0; s < 2; s++) {
            const int kpb = s * 8;
            uint32_t ah[4][4], al[4][4], bh[8][2], bl[8][2];
            #pragma unroll
            for (int mi = 0; mi < 4; mi++) {
                int mo = wm + mi * 16 + r8;
                const uint32_t* p0 = Ahi + (kpb + cc) * S_LD + mo;
                ah[mi][0] = p0[0];
                ah[mi][1] = p0[8];
                ah[mi][2] = p0[4 * S_LD];
                ah[mi][3] = p0[4 * S_LD + 8];
                const uint32_t* p1 = Alo + (kpb + cc) * S_LD + mo;
                al[mi][0] = p1[0];
                al[mi][1] = p1[8];
                al[mi][2] = p1[4 * S_LD];
                al[mi][3] = p1[4 * S_LD + 8];
            }
            #pragma unroll
            for (int ni = 0; ni < 8; ni++) {
                int no = wn + ni * 8 + r8;
                const uint32_t* p0 = Bhi + (kpb + cc) * S_LD + no;
                bh[ni][0] = p0[0];
                bh[ni][1] = p0[4 * S_LD];
                const uint32_t* p1 = Blo + (kpb + cc) * S_LD + no;
                bl[ni][0] = p1[0];
                bl[ni][1] = p1[4 * S_LD];
            }
            #pragma unroll
            for (int mi = 0; mi < 4; mi++)
                #pragma unroll
                for (int ni = 0; ni < 8; ni++) {
                    mma_f16(acc[mi][ni], ah[mi], bh[ni]);
                    mma_f16(acc[mi][ni], ah[mi], bl[ni]);
                    mma_f16(acc[mi][ni], al[mi], bh[ni]);
                }
        }
        __syncthreads();
    }

    #pragma unroll
    for (int mi = 0; mi < 4; mi++) {
        int r = bm + wm + mi * 16 + r8;
        #pragma unroll
        for (int ni = 0; ni < 8; ni++) {
            int col = bn + wn + ni * 8 + cc * 2;
            *(float2*)(C + (size_t)r * L + col) =
                make_float2(acc[mi][ni][0], acc[mi][ni][1]);
            *(float2*)(C + (size_t)(r + 8) * L + col) =
                make_float2(acc[mi][ni][2], acc[mi][ni][3]);
        }
    }
}

// =====================================================================
// 5+6 fused: scores (9-tap + normalize) + fuse1 (diagonal 3-tap),
// writing g_t1 directly.  Block (32,8); output tile 32(q) x 32(p).
// =====================================================================
__global__ void __launch_bounds__(256) k_scores_fuse1() {
    __shared__ float ssc[34][35];
    const int bb = blockIdx.z;
    const int p0 = blockIdx.x * 32, q0 = blockIdx.y * 32;
    const float* M = g_corr + (size_t)bb * L * L;
    const float* rn = g_rnorm + bb * L;
    float* dst = g_t1 + (size_t)bb * L * L;
    const int tid = threadIdx.y * 32 + threadIdx.x;

    for (int idx = tid; idx < 34 * 34; idx += 256) {
        int a = idx / 34, b = idx - a * 34;
        int q = q0 - 1 + a, p = p0 - 1 + b;
        float s = 0.f;
        if (q >= 0 && q < L && p >= 0 && p < L) {
            int qy = q >> 5, qx = q & 31, py = p >> 5, px = p & 31;
            #pragma unroll
            for (int dy = -1; dy <= 1; dy++) {
                int qy2 = qy + dy, py2 = py + dy;
                if (qy2 < 0 || qy2 >= HG || py2 < 0 || py2 >= HG) continue;
                #pragma unroll
                for (int dx = -1; dx <= 1; dx++) {
                    int qx2 = qx + dx, px2 = px + dx;
                    if (qx2 < 0 || qx2 >= HG || px2 < 0 || px2 >= HG) continue;
                    s += M[(size_t)(qy2 * HG + qx2) * L + (py2 * HG + px2)];
                }
            }
            s *= rn[q];
        }
        ssc[a][b] = s;
    }
    __syncthreads();

    int tx = threadIdx.x, ty = threadIdx.y;
    #pragma unroll
    for (int r = 0; r < 4; r++) {
        int a = ty + 8 * r + 1, b = tx + 1;
        float s = ssc[a][b] + ssc[a - 1][b - 1] + ssc[a + 1][b + 1];
        dst[(size_t)(q0 + ty + 8 * r) * L + p0 + tx] = s;
    }
}

// ---- 8. mask gate (batch 0 of mask) ----
__global__ void k_mm(const float* __restrict__ mask) {
    int q = blockIdx.x * blockDim.x + threadIdx.x;
    if (q >= L) return;
    int qy = q >> 5, qx = q & 31;
    float s = 0.f;
    for (int dy = -1; dy <= 1; dy++)
      for (int dx = -1; dx <= 1; dx++) {
        int y = qy + dy, x = qx + dx;
        if (y >= 0 && y < HG && x >= 0 && x < HG)
            s += mask[(size_t)(8 * y) * 256 + 8 * x];
      }
    g_mmk[q] = (s == 0.0f) ? 1.0f : 0.0f;
}

// =====================================================================
// 7+9 fused: fuse pass 2 + softmax over q, writing attn TRANSPOSED
// [p][q] as fp16.  Block (32,32); one block per (hf, batch).
// =====================================================================
__global__ void __launch_bounds__(1024) k_fuse2_softmax() {
    int bb = blockIdx.y, hf = blockIdx.x;
    int tx = threadIdx.x, ty = threadIdx.y;
    const float* T = g_t1 + (size_t)bb * L * L;
    __half* dst = g_attnh + (size_t)bb * L * L;
    __shared__ float red[32][33];

    int col[3]; bool jv[3];
    #pragma unroll
    for (int dd = 0; dd < 3; dd++) {
        int j2 = tx * 32 + hf + dd - 1;
        jv[dd] = (j2 >= 0) && (j2 < L);
        int jj = jv[dd] ? j2 : 0;
        col[dd] = (jj & 31) * 32 + (jj >> 5);
    }

    float v[32];
    float mx = -1e30f;
    #pragma unroll
    for (int i = 0; i < 32; i++) {
        float s = 0.f;
        #pragma unroll
        for (int dd = 0; dd < 3; dd++) {
            int i2 = ty * 32 + i + dd - 1;
            bool iv = (i2 >= 0) && (i2 < L);
            if (iv && jv[dd]) {
                int rowi = (i2 & 31) * 32 + (i2 >> 5);
                s += T[(size_t)rowi * L + col[dd]];
            }
        }
        float vv = s * g_mmk[i * 32 + ty] * 10.0f;
        v[i] = vv;
        mx = fmaxf(mx, vv);
    }

    red[ty][tx] = mx; __syncthreads();
    #pragma unroll
    for (int s = 16; s > 0; s >>= 1) {
        if (ty < s) red[ty][tx] = fmaxf(red[ty][tx], red[ty + s][tx]);
        __syncthreads();
    }
    float m = red[0][tx];
    __syncthreads();

    float sum = 0.f;
    #pragma unroll
    for (int i = 0; i < 32; i++) {
        v[i] = __expf(v[i] - m);
        sum += v[i];
    }
    red[ty][tx] = sum; __syncthreads();
    #pragma unroll
    for (int s = 16; s > 0; s >>= 1) {
        if (ty < s) red[ty][tx] += red[ty + s][tx];
        __syncthreads();
    }
    float inv = 1.0f / red[0][tx];
    __syncthreads();

    // write transposed: dst[p][q] fp16
    #pragma unroll
    for (int i = 0; i < 32; i++) {
        red[ty][tx] = v[i] * inv * g_mmk[i * 32 + ty];
        __syncthreads();
        dst[(size_t)(hf * 32 + ty) * L + i * 32 + tx] = __float2half(red[tx][ty]);
        __syncthreads();
    }
}

// ---- 10. build W fp16, N-major (2 consecutive q per thread) ----
__global__ void k_buildWh(const float* __restrict__ b_in) {
    int idx = blockIdx.x * blockDim.x + threadIdx.x;
    if (idx >= NB*NCOLS*(L/2)) return;
    int q2 = idx & 511;
    int n = (idx >> 9) & (NCOLS - 1);
    int bb = idx >> 20;
    int v = n & 3, u = (n >> 2) & 3, c = n >> 4;
    int q0 = 2 * q2;
    int qy = q0 >> 5, qx = q0 & 31;
    int by = 2 * qy + u - 1;
    int bx0 = 2 * qx + v - 1;
    float v0 = 0.f, v1 = 0.f;
    if (by >= 0 && by < 64) {
        const float* row = b_in + ((size_t)(bb * NC + c)) * 4096 + (size_t)by * 64;
        if (bx0 >= 0 && bx0 < 64)     v0 = row[bx0];
        if (bx0 + 2 >= 0 && bx0 + 2 < 64) v1 = row[bx0 + 2];
    }
    reinterpret_cast<uint32_t*>(g_Wh)[(size_t)(bb * NCOLS + n) * (L/2) + q2] =
        pack_h2(__float2half(v0), __float2half(v1));
}

// =====================================================================
// GEMM2 via fp16 m16n8k16, 3-stage cp.async pipeline, transposed out:
// OP[n,p] = sum_q W[n,q] * attn[p,q]
// A = g_Wh [2048 n][1024 q] row-major, B = g_attnh [1024 p][1024 q]
// N-major.  128x128 CTA tile, 4 warps, BK=64, 16 k-tiles.
// =====================================================================
#define H_LDW 36                       // words per smem row
#define H_STAGE_W (2*128*H_LDW)

__global__ void __launch_bounds__(128, 2)
mma_gemm2h(const __half* __restrict__ Aall, const __half* __restrict__ Ball,
           float* __restrict__ Call) {
    extern __shared__ uint32_t smw[];
    const __half* A = Aall + (size_t)blockIdx.z * (size_t)NCOLS * L;
    const __half* B = Ball + (size_t)blockIdx.z * (size_t)L * L;
    float* C = Call + (size_t)blockIdx.z * (size_t)NCOLS * L;
    const int bm = blockIdx.y * 128, bn = blockIdx.x * 128;
    const int tid = threadIdx.x;
    const int warp = tid >> 5, lane = tid & 31;
    const int wm = (warp & 1) << 6, wn = (warp >> 1) << 6;
    const int r8 = lane >> 2, cc = lane & 3;

    float acc[4][8][4];
    #pragma unroll
    for (int mi = 0; mi < 4; mi++)
      #pragma unroll
      for (int ni = 0; ni < 8; ni++)
        #pragma unroll
        for (int k = 0; k < 4; k++) acc[mi][ni][k] = 0.f;

    const __half* ag = A + (size_t)(bm + tid) * L;
    const __half* bg = B + (size_t)(bn + tid) * L;
    uint32_t smb = (uint32_t)__cvta_generic_to_shared(smw);

    auto load_stage = [&](int buf, int kt) {
        uint32_t sb = smb + (uint32_t)(buf * H_STAGE_W) * 4u;
        const __half* ag_ = ag + kt * 64;
        const __half* bg_ = bg + kt * 64;
        uint32_t as_ = sb + (uint32_t)tid * 144u;
        uint32_t bs_ = sb + 128u * 144u + (uint32_t)tid * 144u;
        #pragma unroll
        for (int i = 0; i < 8; i++) {
            cp_async16(as_ + i * 16, ag_ + i * 8);
            cp_async16(bs_ + i * 16, bg_ + i * 8);
        }
        asm volatile("cp.async.commit_group;");
    };

    load_stage(0, 0);
    load_stage(1, 1);

    const int NKT = 16;
    for (int kt = 0; kt < NKT; kt++) {
        if (kt + 2 < NKT) {
            load_stage((kt + 2) % 3, kt + 2);
            asm volatile("cp.async.wait_group 2;");
        } else if (kt == NKT - 2) {
            asm volatile("cp.async.wait_group 1;");
        } else {
            asm volatile("cp.async.wait_group 0;");
        }
        __syncthreads();

        const uint32_t* As = smw + (kt % 3) * H_STAGE_W;
        const uint32_t* Bs = As + 128 * H_LDW;
        #pragma unroll
        for (int s = 0; s < 4; s++) {
            const int kw = s * 8;
            uint32_t a[4][4], b[8][2];
            #pragma unroll
            for (int mi = 0; mi < 4; mi++) {
                const uint32_t* ap = As + (wm + mi * 16 + r8) * H_LDW + kw + cc;
                a[mi][0] = ap[0];
                a[mi][1] = ap[8 * H_LDW];
                a[mi][2] = ap[4];
                a[mi][3] = ap[8 * H_LDW + 4];
            }
            #pragma unroll
            for (int ni = 0; ni < 8; ni++) {
                const uint32_t* bp = Bs + (wn + ni * 8 + r8) * H_LDW + kw + cc;
                b[ni][0] = bp[0];
                b[ni][1] = bp[4];
            }
            #pragma unroll
            for (int mi = 0; mi < 4; mi++)
                #pragma unroll
                for (int ni = 0; ni < 8; ni++)
                    mma_f16(acc[mi][ni], a[mi], b[ni]);
        }
        __syncthreads();
    }

    #pragma unroll
    for (int mi = 0; mi < 4; mi++) {
        int row = bm + wm + mi * 16 + r8;      // n index
        #pragma unroll
        for (int ni = 0; ni < 8; ni++) {
            int col = bn + wn + ni * 8 + cc * 2;   // p index
            *(float2*)(C + (size_t)row * L + col) =
                make_float2(acc[mi][ni][0], acc[mi][ni][1]);
            *(float2*)(C + (size_t)(row + 8) * L + col) =
                make_float2(acc[mi][ni][2], acc[mi][ni][3]);
        }
    }
}

// ---- 12. overlap-add gather (deconv epilogue); OP is [b][n][p] ----
__global__ void k_gather(float* __restrict__ out) {
    int idx = blockIdx.x * blockDim.x + threadIdx.x;
    if (idx >= NB*NC*4096) return;
    int ox = idx & 63, oy = (idx >> 6) & 63, c = (idx >> 12) & 127, bb = idx >> 19;
    float s = 0.f;
    int ay = (oy + 1) & 1, ax = (ox + 1) & 1;
    const float* OPb = g_OP + (size_t)bb * NCOLS * L;
    #pragma unroll
    for (int uu = 0; uu < 2; uu++) {
        int u = ay + 2 * uu;
        int t = oy + 1 - u;
        if (t < 0) continue;
        int py = t >> 1;
        if (py >= HG) continue;
        #pragma unroll
        for (int vv = 0; vv < 2; vv++) {
            int v = ax + 2 * vv;
            int t2 = ox + 1 - v;
            if (t2 < 0) continue;
            int px = t2 >> 1;
            if (px >= HG) continue;
            s += OPb[(size_t)(c * 16 + u * 4 + v) * L + py * HG + px];
        }
    }
    out[idx] = 0.25f * s;
}

extern "C" void kernel_launch(void* const* d_in, const int* in_sizes, int n_in,
                              void* d_out, int out_size) {
    (void)in_sizes; (void)n_in; (void)out_size;
    const float* f    = (const float*)d_in[0];
    const float* b    = (const float*)d_in[1];
    const float* mask = (const float*)d_in[2];
    float* out = (float*)d_out;

    float *p_corr, *p_OP;
    uint32_t *p_bdh, *p_bdl, *p_fdh, *p_fdl;
    __half *p_attnh, *p_Wh;
    cudaGetSymbolAddress((void**)&p_corr,  g_corr);
    cudaGetSymbolAddress((void**)&p_bdh,   g_bdh);
    cudaGetSymbolAddress((void**)&p_bdl,   g_bdl);
    cudaGetSymbolAddress((void**)&p_fdh,   g_fdh);
    cudaGetSymbolAddress((void**)&p_fdl,   g_fdl);
    cudaGetSymbolAddress((void**)&p_attnh, g_attnh);
    cudaGetSymbolAddress((void**)&p_Wh,    g_Wh);
    cudaGetSymbolAddress((void**)&p_OP,    g_OP);

    const int g1_smem = 3 * G1_STAGE * 4;    // 104448 bytes
    const int g2_smem = 3 * H_STAGE_W * 4;   // 110592 bytes
    cudaFuncSetAttribute(mma_gemm1h, cudaFuncAttributeMaxDynamicSharedMemorySize, g1_smem);
    cudaFuncSetAttribute(mma_gemm2h, cudaFuncAttributeMaxDynamicSharedMemorySize, g2_smem);

    k_down_split<<<(NB*KP*L + 255) / 256, 256>>>(f, b);
    k_ssq<<<(NB*L + 255) / 256, 256>>>();
    k_rnorm<<<(NB*L + 255) / 256, 256>>>();

    // GEMM1: corr[q,p] (M=N=1024, K=128 channels) — 3x fp16-split MMA
    {
        dim3 grid(L / 128, L / 128, NB);
        mma_gemm1h<<<grid, 128, g1_smem>>>(p_bdh, p_bdl, p_fdh, p_fdl, p_corr);
    }

    // fused scores + fuse1
    {
        dim3 grid(32, 32, NB);
        dim3 blk(32, 8);
        k_scores_fuse1<<<grid, blk>>>();
    }
    k_mm<<<(L + 255) / 256, 256>>>(mask);
    {
        dim3 grid(32, NB);
        dim3 blk(32, 32);
        k_fuse2_softmax<<<grid, blk>>>();
    }
    k_buildWh<<<(NB*NCOLS*(L/2) + 255) / 256, 256>>>(b);

    // GEMM2: OP[n,p] (M=2048, N=1024, K=1024) — fp16 MMA, transposed out
    {
        dim3 grid(L / 128, NCOLS / 128, NB);
        mma_gemm2h<<<grid, 128, g2_smem>>>(p_Wh, p_attnh, p_OP);
    }

    k_gather<<<(NB*NC*4096 + 255) / 256, 256>>>(out);
}